// round 4
// baseline (speedup 1.0000x reference)
#include <cuda_runtime.h>
#include <math.h>

#define SS   4
#define NN   5000
#define LL   8
#define INF_ 128
#define OO   128
#define EFD  64
#define NEG  80000
#define DIN_ 385
#define BB   20000
#define GG   384

// ---------------- device scratch (static; no allocs allowed) ----------------
__device__ __align__(16) float g_u2[LL * BB * 2];
__device__ __align__(16) float g_Wt4_f[32 * GG * 4];
__device__ __align__(16) float g_Wt4_b[32 * GG * 4];
__device__ __align__(16) float g_Wt4_m[32 * GG * 4];
__device__ __align__(16) float g_WA4[32 * GG * 4];
__device__ __align__(16) float g_WB4[32 * GG * 4];
__device__ __align__(16) float g_WC4[32 * GG * 4];
__device__ __align__(16) float g_Wcomb4[16 * GG * 4];
__device__ __align__(16) float g_wD[GG];
__device__ __align__(16) float g_EG[NEG * GG];        // e @ (Wih*W_e)^T   [80000,384]
__device__ __align__(16) float g_HG[NN * GG];         // h @ WihA^T        [5000,384]
__device__ __align__(16) float g_yf[LL * BB * OO];    // forward walk GRU outputs
__device__ __align__(16) float g_yb[LL * BB * OO];    // backward walk GRU outputs
__device__ __align__(16) float g_XGe[LL * BB * GG];   // even-step input gates
__device__ __align__(16) float g_h0[BB * OO];
__device__ __align__(16) float g_h1[BB * OO];
__device__ int g_degmax;

__device__ __forceinline__ float sigf(float x) { return 1.0f / (1.0f + expf(-x)); }

// ---------------------------------------------------------------------------
// Core: 16-row x 384-col GEMM tile. 128 threads; thread j owns gate columns
// j, 128+j, 256+j for 16 batch rows. A-tile in smem (broadcast float4 reads),
// W pre-transposed/packed as Wt4[k/4][384][4] so each thread does 3 LDG.128 +
// 16 LDS.128 per 192 FMAs.
// ---------------------------------------------------------------------------
template <int KD4>
__device__ __forceinline__ void gemm_tile16(
    const float* __restrict__ sh, const float* __restrict__ Wt4, int j,
    float (&aR)[16], float (&aZ)[16], float (&aN)[16])
{
#pragma unroll 2
    for (int k4 = 0; k4 < KD4; ++k4) {
        const float4 wa = *reinterpret_cast<const float4*>(Wt4 + ((size_t)k4 * GG + j) * 4);
        const float4 wb = *reinterpret_cast<const float4*>(Wt4 + ((size_t)k4 * GG + 128 + j) * 4);
        const float4 wc = *reinterpret_cast<const float4*>(Wt4 + ((size_t)k4 * GG + 256 + j) * 4);
#pragma unroll
        for (int r = 0; r < 16; ++r) {
            const float4 hv = *reinterpret_cast<const float4*>(sh + r * (KD4 * 4) + k4 * 4);
            aR[r] = fmaf(hv.x, wa.x, aR[r]); aR[r] = fmaf(hv.y, wa.y, aR[r]);
            aR[r] = fmaf(hv.z, wa.z, aR[r]); aR[r] = fmaf(hv.w, wa.w, aR[r]);
            aZ[r] = fmaf(hv.x, wb.x, aZ[r]); aZ[r] = fmaf(hv.y, wb.y, aZ[r]);
            aZ[r] = fmaf(hv.z, wb.z, aZ[r]); aZ[r] = fmaf(hv.w, wb.w, aZ[r]);
            aN[r] = fmaf(hv.x, wc.x, aN[r]); aN[r] = fmaf(hv.y, wc.y, aN[r]);
            aN[r] = fmaf(hv.z, wc.z, aN[r]); aN[r] = fmaf(hv.w, wc.w, aN[r]);
        }
    }
}

// ---------------- small prep kernels ----------------
// pack W[384 x K] (row-major, possibly a column slice of Wih) into Wt4 layout
__global__ void transpose_w4_kernel(const float* __restrict__ W, int ldw, int koff, int which)
{
    int idx = blockIdx.x * 256 + threadIdx.x;
    if (idx >= GG * 128) return;
    int g = idx >> 7;
    int k = idx & 127;
    float v = W[(size_t)g * ldw + koff + k];
    float* dst = which == 0 ? g_Wt4_f : which == 1 ? g_Wt4_b : which == 2 ? g_Wt4_m
               : which == 3 ? g_WA4  : which == 4 ? g_WB4  : g_WC4;
    dst[(((size_t)(k >> 2)) * GG + g) * 4 + (k & 3)] = v;
}

// Wcomb[g,c] = sum_d Wih[g,d] * W_e[d,c]  (fold edge projection into Wih)
__global__ void wcomb_kernel(const float* __restrict__ Wih, const float* __restrict__ We)
{
    int idx = blockIdx.x * 256 + threadIdx.x;
    if (idx >= GG * EFD) return;
    int g = idx / EFD, c = idx % EFD;
    float s = 0.f;
    for (int d = 0; d < DIN_; ++d)
        s = fmaf(Wih[(size_t)g * DIN_ + d], We[(size_t)d * EFD + c], s);
    g_Wcomb4[(((size_t)(c >> 2)) * GG + g) * 4 + (c & 3)] = s;
    if (c == 0) g_wD[g] = Wih[(size_t)g * DIN_ + (DIN_ - 1)];
}

__global__ void degmax_init_kernel() { if (threadIdx.x == 0) g_degmax = 0; }

__global__ void degmax_kernel(const int* __restrict__ walks, const int* __restrict__ deg)
{
    int i = blockIdx.x * 256 + threadIdx.x;
    int v = 0;
    if (i < SS * NN * LL) v = deg[walks[i]];
    for (int off = 16; off; off >>= 1) v = max(v, __shfl_xor_sync(0xffffffffu, v, off));
    if ((threadIdx.x & 31) == 0) atomicMax(&g_degmax, v);
}

// uniqueness encoding -> sin/cos, time-flipped, layout [L][B][2]
__global__ void u2_kernel(const int* __restrict__ walks)
{
    int b = blockIdx.x * 128 + threadIdx.x;
    if (b >= BB) return;
    int w[LL];
#pragma unroll
    for (int t = 0; t < LL; ++t) w[t] = walks[(size_t)b * LL + t];
#pragma unroll
    for (int t2 = 0; t2 < LL; ++t2) {
        int t = LL - 1 - t2;               // flipped position
        int f = t;
#pragma unroll
        for (int jj = LL - 1; jj >= 0; --jj)
            if (jj <= t && w[jj] == w[t]) f = jj;   // min index with match
        float a = (float)f * (6.283185307179586f / (float)LL);
        g_u2[((size_t)t2 * BB + b) * 2]     = sinf(a);
        g_u2[((size_t)t2 * BB + b) * 2 + 1] = cosf(a);
    }
}

// ---------------- big precompute GEMMs: EG (K=64) and HG (K=128) ----------------
template <int MODE>   // 0: EG (A=e, W=Wcomb4, M=NEG)   1: HG (A=h, W=WA4, M=NN)
__global__ void __launch_bounds__(128) gemm3_kernel(const float* __restrict__ A)
{
    constexpr int KD4 = (MODE == 0) ? 16 : 32;
    constexpr int K   = KD4 * 4;
    const float* Wt4 = (MODE == 0) ? g_Wcomb4 : g_WA4;
    float*       C   = (MODE == 0) ? g_EG : g_HG;
    const int    M   = (MODE == 0) ? NEG : NN;

    __shared__ __align__(16) float sh[16 * K];
    const int j  = threadIdx.x;
    const int b0 = blockIdx.x * 16;
    const int lim = (M - b0) * K;
    for (int i = j; i < 16 * K; i += 128)
        sh[i] = (i < lim) ? A[(size_t)b0 * K + i] : 0.f;
    __syncthreads();

    float aR[16], aZ[16], aN[16];
#pragma unroll
    for (int r = 0; r < 16; ++r) { aR[r] = 0.f; aZ[r] = 0.f; aN[r] = 0.f; }
    gemm_tile16<KD4>(sh, Wt4, j, aR, aZ, aN);

#pragma unroll
    for (int r = 0; r < 16; ++r) {
        if (b0 + r < M) {
            float* o = C + (size_t)(b0 + r) * GG;
            o[j] = aR[r]; o[128 + j] = aZ[r]; o[256 + j] = aN[r];
        }
    }
}

// ---------------- walk GRU step (forward/backward), fused gates ----------------
__global__ void __launch_bounds__(128) walk_step_kernel(
    int t, int backward,
    const float* __restrict__ Wih2, const float* __restrict__ bih,
    const float* __restrict__ bhh)
{
    __shared__ __align__(16) float sh[16 * 128];
    __shared__ float shu[32];
    const int j  = threadIdx.x;
    const int b0 = blockIdx.x * 16;
    float*       ybuf = backward ? g_yb : g_yf;
    const float* Wt4  = backward ? g_Wt4_b : g_Wt4_f;
    const float* hprev = (t == 0) ? (const float*)0 : (ybuf + (size_t)(t - 1) * BB * OO);
    const int tin = backward ? (LL - 1 - t) : t;
    const float* u2t = g_u2 + (size_t)tin * BB * 2;

    if (hprev) {
        const float* src = hprev + (size_t)b0 * OO;
#pragma unroll
        for (int i = 0; i < 16; ++i) sh[j + i * 128] = src[j + i * 128];
    } else {
#pragma unroll
        for (int i = 0; i < 16; ++i) sh[j + i * 128] = 0.f;
    }
    if (j < 32) shu[j] = u2t[(size_t)b0 * 2 + j];
    __syncthreads();

    float aR[16], aZ[16], aN[16];
#pragma unroll
    for (int r = 0; r < 16; ++r) { aR[r] = 0.f; aZ[r] = 0.f; aN[r] = 0.f; }
    if (hprev) gemm_tile16<32>(sh, Wt4, j, aR, aZ, aN);

    const float wr0 = Wih2[2 * j],         wr1 = Wih2[2 * j + 1];
    const float wz0 = Wih2[2 * (128 + j)], wz1 = Wih2[2 * (128 + j) + 1];
    const float wn0 = Wih2[2 * (256 + j)], wn1 = Wih2[2 * (256 + j) + 1];
    const float br = bih[j], bz = bih[128 + j], bn = bih[256 + j];
    const float cr = bhh[j], cz = bhh[128 + j], cn = bhh[256 + j];
    float* yo = ybuf + (size_t)t * BB * OO + (size_t)b0 * OO + j;
#pragma unroll
    for (int r = 0; r < 16; ++r) {
        float u = shu[2 * r], v = shu[2 * r + 1];
        float rg = sigf(fmaf(wr0, u, fmaf(wr1, v, br)) + aR[r] + cr);
        float zg = sigf(fmaf(wz0, u, fmaf(wz1, v, bz)) + aZ[r] + cz);
        float ng = tanhf(fmaf(wn0, u, fmaf(wn1, v, bn)) + rg * (aN[r] + cn));
        yo[r * 128] = (1.f - zg) * ng + zg * sh[r * 128 + j];
    }
}

__global__ void hwalk_kernel()
{
    int i = blockIdx.x * 256 + threadIdx.x;
    if (i < BB * OO)
        g_h0[i] = 0.5f * (g_yf[(size_t)(LL - 1) * BB * OO + i] +
                          g_yb[(size_t)(LL - 1) * BB * OO + i]);
}

// ---------------- even-step input gates: XGe = yf@WB^T + yb_flip@WC^T + HG[node] + deg*wD + bih
__global__ void __launch_bounds__(128) xge_kernel(
    const int* __restrict__ walks, const int* __restrict__ deg,
    const float* __restrict__ bih)
{
    __shared__ __align__(16) float shf[2048];
    __shared__ __align__(16) float shb[2048];
    __shared__ int   shn[16];
    __shared__ float shd[16];
    const int j  = threadIdx.x;
    const int b0 = blockIdx.x * 16;
    const int p  = blockIdx.y;

    {
        const float* f = g_yf + ((size_t)p * BB + b0) * OO;
        const float* bsrc = g_yb + ((size_t)(LL - 1 - p) * BB + b0) * OO;
#pragma unroll
        for (int i = 0; i < 16; ++i) {
            shf[j + i * 128] = f[j + i * 128];
            shb[j + i * 128] = bsrc[j + i * 128];
        }
    }
    if (j < 16) {
        int node = walks[(size_t)(b0 + j) * LL + (LL - 1 - p)];
        shn[j] = node;
        int dm = g_degmax;
        shd[j] = (dm > 0) ? ((float)deg[node] / (float)dm) : 0.f;
    }
    __syncthreads();

    float aR[16], aZ[16], aN[16];
#pragma unroll
    for (int r = 0; r < 16; ++r) { aR[r] = 0.f; aZ[r] = 0.f; aN[r] = 0.f; }
    gemm_tile16<32>(shf, g_WB4, j, aR, aZ, aN);
    gemm_tile16<32>(shb, g_WC4, j, aR, aZ, aN);

    const float wdr = g_wD[j], wdz = g_wD[128 + j], wdn = g_wD[256 + j];
    const float br = bih[j], bz = bih[128 + j], bn = bih[256 + j];
    float* out = g_XGe + ((size_t)p * BB + b0) * GG;
#pragma unroll
    for (int r = 0; r < 16; ++r) {
        const float* hg = g_HG + (size_t)shn[r] * GG;
        float d = shd[r];
        out[(size_t)r * GG + j]       = aR[r] + hg[j]       + d * wdr + br;
        out[(size_t)r * GG + 128 + j] = aZ[r] + hg[128 + j] + d * wdz + bz;
        out[(size_t)r * GG + 256 + j] = aN[r] + hg[256 + j] + d * wdn + bn;
    }
}

// ---------------- main GRU step (15 steps), fused gates ----------------
__global__ void __launch_bounds__(128) main_step_kernel(
    int t, const int* __restrict__ eids,
    const float* __restrict__ bih, const float* __restrict__ bhh,
    float* __restrict__ dout)
{
    __shared__ __align__(16) float sh[16 * 128];
    const int j  = threadIdx.x;
    const int b0 = blockIdx.x * 16;
    const float* hin  = (t & 1) ? g_h1 : g_h0;
    float*       hout = (t == 14) ? dout : ((t & 1) ? g_h0 : g_h1);

    {
        const float* src = hin + (size_t)b0 * OO;
#pragma unroll
        for (int i = 0; i < 16; ++i) sh[j + i * 128] = src[j + i * 128];
    }
    __syncthreads();

    float aR[16], aZ[16], aN[16];
#pragma unroll
    for (int r = 0; r < 16; ++r) { aR[r] = 0.f; aZ[r] = 0.f; aN[r] = 0.f; }
    gemm_tile16<32>(sh, g_Wt4_m, j, aR, aZ, aN);

    const float cr = bhh[j], cz = bhh[128 + j], cn = bhh[256 + j];
    if ((t & 1) == 0) {
        const int p = t >> 1;
        const float* xg = g_XGe + ((size_t)p * BB + b0) * GG;
#pragma unroll
        for (int r = 0; r < 16; ++r) {
            const float* x = xg + (size_t)r * GG;
            float rg = sigf(x[j] + aR[r] + cr);
            float zg = sigf(x[128 + j] + aZ[r] + cz);
            float ng = tanhf(x[256 + j] + rg * (aN[r] + cn));
            hout[(size_t)(b0 + r) * OO + j] = (1.f - zg) * ng + zg * sh[r * 128 + j];
        }
    } else {
        const int p = (t - 1) >> 1;
        const float br = bih[j], bz = bih[128 + j], bn = bih[256 + j];
#pragma unroll
        for (int r = 0; r < 16; ++r) {
            int eid = eids[(size_t)(b0 + r) * (LL - 1) + p];
            const float* x = g_EG + (size_t)eid * GG;
            float rg = sigf(x[j] + br + aR[r] + cr);
            float zg = sigf(x[128 + j] + bz + aZ[r] + cz);
            float ng = tanhf(x[256 + j] + bn + rg * (aN[r] + cn));
            hout[(size_t)(b0 + r) * OO + j] = (1.f - zg) * ng + zg * sh[r * 128 + j];
        }
    }
}

// ---------------------------------------------------------------------------
extern "C" void kernel_launch(void* const* d_in, const int* in_sizes, int n_in,
                              void* d_out, int out_size)
{
    (void)in_sizes; (void)n_in; (void)out_size;
    const float* h     = (const float*)d_in[0];
    const float* e     = (const float*)d_in[1];
    const float* W_e   = (const float*)d_in[2];
    const float* Wih_f = (const float*)d_in[3];
    const float* Whh_f = (const float*)d_in[4];
    const float* bih_f = (const float*)d_in[5];
    const float* bhh_f = (const float*)d_in[6];
    const float* Wih_b = (const float*)d_in[7];
    const float* Whh_b = (const float*)d_in[8];
    const float* bih_b = (const float*)d_in[9];
    const float* bhh_b = (const float*)d_in[10];
    const float* Wih   = (const float*)d_in[11];
    const float* Whh   = (const float*)d_in[12];
    const float* bih   = (const float*)d_in[13];
    const float* bhh   = (const float*)d_in[14];
    const int*   walks = (const int*)d_in[15];
    const int*   eids  = (const int*)d_in[16];
    const int*   deg   = (const int*)d_in[17];
    float* out = (float*)d_out;

    // weight packing / precombination
    transpose_w4_kernel<<<192, 256>>>(Whh_f, 128, 0,   0);
    transpose_w4_kernel<<<192, 256>>>(Whh_b, 128, 0,   1);
    transpose_w4_kernel<<<192, 256>>>(Whh,   128, 0,   2);
    transpose_w4_kernel<<<192, 256>>>(Wih,   385, 0,   3);
    transpose_w4_kernel<<<192, 256>>>(Wih,   385, 128, 4);
    transpose_w4_kernel<<<192, 256>>>(Wih,   385, 256, 5);
    wcomb_kernel<<<(GG * EFD + 255) / 256, 256>>>(Wih, W_e);
    degmax_init_kernel<<<1, 32>>>();
    degmax_kernel<<<(SS * NN * LL + 255) / 256, 256>>>(walks, deg);
    u2_kernel<<<(BB + 127) / 128, 128>>>(walks);

    // big precompute GEMMs
    gemm3_kernel<0><<<NEG / 16, 128>>>(e);            // EG [80000,384]
    gemm3_kernel<1><<<(NN + 15) / 16, 128>>>(h);      // HG [5000,384]

    // bidirectional walk GRU (8 steps each direction)
    for (int t = 0; t < LL; ++t) {
        walk_step_kernel<<<BB / 16, 128>>>(t, 0, Wih_f, bih_f, bhh_f);
        walk_step_kernel<<<BB / 16, 128>>>(t, 1, Wih_b, bih_b, bhh_b);
    }
    hwalk_kernel<<<(BB * OO + 255) / 256, 256>>>();

    // even-step input gates (one fused GEMM over all 8 walk positions)
    dim3 xg_grid(BB / 16, LL);
    xge_kernel<<<xg_grid, 128>>>(walks, deg, bih);

    // main GRU over interleaved sequence (15 steps), last step writes d_out
    for (int t = 0; t < 2 * LL - 1; ++t)
        main_step_kernel<<<BB / 16, 128>>>(t, eids, bih, bhh, out);
}

// round 5
// speedup vs baseline: 1.0326x; 1.0326x over previous
#include <cuda_runtime.h>
#include <math.h>

#define SS   4
#define NN   5000
#define LL   8
#define OO   128
#define EFD  64
#define NEG  80000
#define DIN_ 385
#define BB   20000
#define GG   384

typedef unsigned long long u64;

// ---------------- device scratch (static; no allocs allowed) ----------------
__device__ __align__(16) float g_u2[LL * BB * 2];
__device__ __align__(16) float g_Wt4_f[32 * GG * 4];
__device__ __align__(16) float g_Wt4_b[32 * GG * 4];
__device__ __align__(16) float g_Wt4_m[32 * GG * 4];
__device__ __align__(16) float g_WA4[32 * GG * 4];
__device__ __align__(16) float g_WB4[32 * GG * 4];
__device__ __align__(16) float g_WC4[32 * GG * 4];
__device__ __align__(16) float g_Wcomb4[16 * GG * 4];
__device__ __align__(16) float g_wD[GG];
__device__ __align__(16) float g_EG[NEG * GG];        // e @ (Wih*W_e)^T   [80000,384]
__device__ __align__(16) float g_HG[NN * GG];         // h @ WihA^T        [5000,384]
__device__ __align__(16) float g_yf[LL * BB * OO];    // forward walk GRU outputs
__device__ __align__(16) float g_yb[LL * BB * OO];    // backward walk GRU outputs
__device__ __align__(16) float g_XGe[LL * BB * GG];   // even-step input gates
__device__ __align__(16) float g_h0[BB * OO];
__device__ __align__(16) float g_h1[BB * OO];
__device__ int g_degmax;

__device__ __forceinline__ float sigf(float x) { return 1.0f / (1.0f + expf(-x)); }

// ---------------- packed f32x2 helpers (Blackwell FFMA2 path) ----------------
__device__ __forceinline__ void ffma2(u64& d, u64 a, u64 b) {
    asm("fma.rn.f32x2 %0, %1, %2, %0;" : "+l"(d) : "l"(a), "l"(b));
}
__device__ __forceinline__ u64 dup2(float w) {
    u64 r; asm("mov.b64 %0, {%1, %1};" : "=l"(r) : "f"(w)); return r;
}
__device__ __forceinline__ u64 pack2u(unsigned x, unsigned y) {
    u64 r; asm("mov.b64 %0, {%1, %2};" : "=l"(r) : "r"(x), "r"(y)); return r;
}
__device__ __forceinline__ float2 unpack2(u64 v) {
    float2 r; asm("mov.b64 {%0, %1}, %2;" : "=f"(r.x), "=f"(r.y) : "l"(v)); return r;
}

// ---------------------------------------------------------------------------
// Core: 16-row x 384-col GEMM tile using packed f32x2 FMA.
// shT: A-tile transposed k-major, layout shT[k*20 + row] (stride 20 floats ->
// 16B-aligned LDS.128, rows 4q..4q+3 per load). 128 threads; thread j owns
// gate columns j, 128+j, 256+j. Accumulators pack row pairs (2p, 2p+1).
// Weights in Wt4[k/4][384][4] float layout, duplicated into {w,w} registers.
// ---------------------------------------------------------------------------
#define ROWP 20

template <int KD4>
__device__ __forceinline__ void gemm2_tile16(
    const float* __restrict__ shT, const float* __restrict__ Wt4, int j,
    u64 (&aR)[8], u64 (&aZ)[8], u64 (&aN)[8])
{
#pragma unroll 2
    for (int k4 = 0; k4 < KD4; ++k4) {
        const float4 wa = *reinterpret_cast<const float4*>(Wt4 + ((size_t)k4 * GG + j) * 4);
        const float4 wb = *reinterpret_cast<const float4*>(Wt4 + ((size_t)k4 * GG + 128 + j) * 4);
        const float4 wc = *reinterpret_cast<const float4*>(Wt4 + ((size_t)k4 * GG + 256 + j) * 4);
        const float wfa[4] = {wa.x, wa.y, wa.z, wa.w};
        const float wfb[4] = {wb.x, wb.y, wb.z, wb.w};
        const float wfc[4] = {wc.x, wc.y, wc.z, wc.w};
#pragma unroll
        for (int kk = 0; kk < 4; ++kk) {
            const u64 dra = dup2(wfa[kk]);
            const u64 drb = dup2(wfb[kk]);
            const u64 drc = dup2(wfc[kk]);
            const uint4* ab = reinterpret_cast<const uint4*>(shT + (size_t)(k4 * 4 + kk) * ROWP);
#pragma unroll
            for (int q = 0; q < 4; ++q) {
                const uint4 v = ab[q];
                const u64 a0 = pack2u(v.x, v.y);
                const u64 a1 = pack2u(v.z, v.w);
                ffma2(aR[2 * q],     a0, dra);
                ffma2(aR[2 * q + 1], a1, dra);
                ffma2(aZ[2 * q],     a0, drb);
                ffma2(aZ[2 * q + 1], a1, drb);
                ffma2(aN[2 * q],     a0, drc);
                ffma2(aN[2 * q + 1], a1, drc);
            }
        }
    }
}

// ---------------- small prep kernels ----------------
__global__ void transpose_w4_kernel(const float* __restrict__ W, int ldw, int koff, int which)
{
    int idx = blockIdx.x * 256 + threadIdx.x;
    if (idx >= GG * 128) return;
    int g = idx >> 7;
    int k = idx & 127;
    float v = W[(size_t)g * ldw + koff + k];
    float* dst = which == 0 ? g_Wt4_f : which == 1 ? g_Wt4_b : which == 2 ? g_Wt4_m
               : which == 3 ? g_WA4  : which == 4 ? g_WB4  : g_WC4;
    dst[(((size_t)(k >> 2)) * GG + g) * 4 + (k & 3)] = v;
}

__global__ void wcomb_kernel(const float* __restrict__ Wih, const float* __restrict__ We)
{
    int idx = blockIdx.x * 256 + threadIdx.x;
    if (idx >= GG * EFD) return;
    int g = idx / EFD, c = idx % EFD;
    float s = 0.f;
    for (int d = 0; d < DIN_; ++d)
        s = fmaf(Wih[(size_t)g * DIN_ + d], We[(size_t)d * EFD + c], s);
    g_Wcomb4[(((size_t)(c >> 2)) * GG + g) * 4 + (c & 3)] = s;
    if (c == 0) g_wD[g] = Wih[(size_t)g * DIN_ + (DIN_ - 1)];
}

__global__ void degmax_init_kernel() { if (threadIdx.x == 0) g_degmax = 0; }

__global__ void degmax_kernel(const int* __restrict__ walks, const int* __restrict__ deg)
{
    int i = blockIdx.x * 256 + threadIdx.x;
    int v = 0;
    if (i < SS * NN * LL) v = deg[walks[i]];
    for (int off = 16; off; off >>= 1) v = max(v, __shfl_xor_sync(0xffffffffu, v, off));
    if ((threadIdx.x & 31) == 0) atomicMax(&g_degmax, v);
}

__global__ void u2_kernel(const int* __restrict__ walks)
{
    int b = blockIdx.x * 128 + threadIdx.x;
    if (b >= BB) return;
    int w[LL];
#pragma unroll
    for (int t = 0; t < LL; ++t) w[t] = walks[(size_t)b * LL + t];
#pragma unroll
    for (int t2 = 0; t2 < LL; ++t2) {
        int t = LL - 1 - t2;               // flipped position
        int f = t;
#pragma unroll
        for (int jj = LL - 1; jj >= 0; --jj)
            if (jj <= t && w[jj] == w[t]) f = jj;   // min index with match
        float a = (float)f * (6.283185307179586f / (float)LL);
        g_u2[((size_t)t2 * BB + b) * 2]     = sinf(a);
        g_u2[((size_t)t2 * BB + b) * 2 + 1] = cosf(a);
    }
}

// ---------------- big precompute GEMMs: EG (K=64) and HG (K=128) ----------------
template <int MODE>   // 0: EG (A=e, W=Wcomb4, M=NEG)   1: HG (A=h, W=WA4, M=NN)
__global__ void __launch_bounds__(128) gemm3_kernel(const float* __restrict__ A)
{
    constexpr int KD4 = (MODE == 0) ? 16 : 32;
    constexpr int K   = KD4 * 4;
    const float* Wt4 = (MODE == 0) ? g_Wcomb4 : g_WA4;
    float*       C   = (MODE == 0) ? g_EG : g_HG;
    const int    M   = (MODE == 0) ? NEG : NN;

    __shared__ __align__(16) float shT[K * ROWP];
    const int j  = threadIdx.x;
    const int b0 = blockIdx.x * 16;
    for (int idx = j; idx < 16 * K; idx += 128) {
        int row = idx / K;
        int k   = idx - row * K;
        float v = (b0 + row < M) ? A[(size_t)(b0 + row) * K + k] : 0.f;
        shT[(size_t)k * ROWP + row] = v;
    }
    __syncthreads();

    u64 aR[8], aZ[8], aN[8];
#pragma unroll
    for (int p = 0; p < 8; ++p) { aR[p] = 0ull; aZ[p] = 0ull; aN[p] = 0ull; }
    gemm2_tile16<KD4>(shT, Wt4, j, aR, aZ, aN);

#pragma unroll
    for (int p = 0; p < 8; ++p) {
        float2 r = unpack2(aR[p]);
        float2 z = unpack2(aZ[p]);
        float2 n = unpack2(aN[p]);
        if (b0 + 2 * p < M) {
            float* o = C + (size_t)(b0 + 2 * p) * GG;
            o[j] = r.x; o[128 + j] = z.x; o[256 + j] = n.x;
        }
        if (b0 + 2 * p + 1 < M) {
            float* o = C + (size_t)(b0 + 2 * p + 1) * GG;
            o[j] = r.y; o[128 + j] = z.y; o[256 + j] = n.y;
        }
    }
}

// ---------------- walk GRU step, forward+backward fused (grid.y=2) ----------------
__global__ void __launch_bounds__(128) walk_step_kernel(
    int t,
    const float* __restrict__ Wih2_f, const float* __restrict__ bih_f,
    const float* __restrict__ bhh_f,
    const float* __restrict__ Wih2_b, const float* __restrict__ bih_b,
    const float* __restrict__ bhh_b)
{
    __shared__ __align__(16) float shT[128 * ROWP];
    __shared__ __align__(16) float shu[32];
    const int j  = threadIdx.x;
    const int b0 = blockIdx.x * 16;
    const int backward = blockIdx.y;

    float*       ybuf = backward ? g_yb : g_yf;
    const float* Wt4  = backward ? g_Wt4_b : g_Wt4_f;
    const float* Wih2 = backward ? Wih2_b : Wih2_f;
    const float* bih  = backward ? bih_b : bih_f;
    const float* bhh  = backward ? bhh_b : bhh_f;
    const int tin = backward ? (LL - 1 - t) : t;
    const float* u2t = g_u2 + (size_t)tin * BB * 2;

    float hv[16];
    if (t > 0) {
        const float* src = ybuf + (size_t)(t - 1) * BB * OO + (size_t)b0 * OO;
#pragma unroll
        for (int i = 0; i < 16; ++i) {
            hv[i] = src[(size_t)i * 128 + j];
            shT[(size_t)j * ROWP + i] = hv[i];
        }
    } else {
#pragma unroll
        for (int i = 0; i < 16; ++i) hv[i] = 0.f;
    }
    if (j < 32) shu[j] = u2t[(size_t)b0 * 2 + j];
    __syncthreads();

    u64 aR[8], aZ[8], aN[8];
#pragma unroll
    for (int p = 0; p < 8; ++p) { aR[p] = 0ull; aZ[p] = 0ull; aN[p] = 0ull; }
    if (t > 0) gemm2_tile16<32>(shT, Wt4, j, aR, aZ, aN);

    const float wr0 = Wih2[2 * j],         wr1 = Wih2[2 * j + 1];
    const float wz0 = Wih2[2 * (128 + j)], wz1 = Wih2[2 * (128 + j) + 1];
    const float wn0 = Wih2[2 * (256 + j)], wn1 = Wih2[2 * (256 + j) + 1];
    const float br = bih[j], bz = bih[128 + j], bn = bih[256 + j];
    const float cr = bhh[j], cz = bhh[128 + j], cn = bhh[256 + j];
    float* yo = ybuf + (size_t)t * BB * OO + (size_t)b0 * OO + j;
#pragma unroll
    for (int p = 0; p < 8; ++p) {
        const float4 uv = *reinterpret_cast<const float4*>(shu + 4 * p);
        float2 fR = unpack2(aR[p]);
        float2 fZ = unpack2(aZ[p]);
        float2 fN = unpack2(aN[p]);
        {
            float rg = sigf(fmaf(wr0, uv.x, fmaf(wr1, uv.y, br)) + fR.x + cr);
            float zg = sigf(fmaf(wz0, uv.x, fmaf(wz1, uv.y, bz)) + fZ.x + cz);
            float ng = tanhf(fmaf(wn0, uv.x, fmaf(wn1, uv.y, bn)) + rg * (fN.x + cn));
            yo[(size_t)(2 * p) * 128] = (1.f - zg) * ng + zg * hv[2 * p];
        }
        {
            float rg = sigf(fmaf(wr0, uv.z, fmaf(wr1, uv.w, br)) + fR.y + cr);
            float zg = sigf(fmaf(wz0, uv.z, fmaf(wz1, uv.w, bz)) + fZ.y + cz);
            float ng = tanhf(fmaf(wn0, uv.z, fmaf(wn1, uv.w, bn)) + rg * (fN.y + cn));
            yo[(size_t)(2 * p + 1) * 128] = (1.f - zg) * ng + zg * hv[2 * p + 1];
        }
    }
}

__global__ void hwalk_kernel()
{
    int i = blockIdx.x * 256 + threadIdx.x;
    if (i < BB * OO)
        g_h0[i] = 0.5f * (g_yf[(size_t)(LL - 1) * BB * OO + i] +
                          g_yb[(size_t)(LL - 1) * BB * OO + i]);
}

// ---------------- even-step input gates: XGe = yf@WB^T + yb_flip@WC^T + HG[node] + deg*wD + bih
__global__ void __launch_bounds__(128) xge_kernel(
    const int* __restrict__ walks, const int* __restrict__ deg,
    const float* __restrict__ bih)
{
    __shared__ __align__(16) float shf[128 * ROWP];
    __shared__ __align__(16) float shb[128 * ROWP];
    __shared__ int   shn[16];
    __shared__ float shd[16];
    const int j  = threadIdx.x;
    const int b0 = blockIdx.x * 16;
    const int p_ = blockIdx.y;

    {
        const float* f    = g_yf + ((size_t)p_ * BB + b0) * OO;
        const float* bsrc = g_yb + ((size_t)(LL - 1 - p_) * BB + b0) * OO;
#pragma unroll
        for (int i = 0; i < 16; ++i) {
            shf[(size_t)j * ROWP + i] = f[(size_t)i * 128 + j];
            shb[(size_t)j * ROWP + i] = bsrc[(size_t)i * 128 + j];
        }
    }
    if (j < 16) {
        int node = walks[(size_t)(b0 + j) * LL + (LL - 1 - p_)];
        shn[j] = node;
        int dm = g_degmax;
        shd[j] = (dm > 0) ? ((float)deg[node] / (float)dm) : 0.f;
    }
    __syncthreads();

    u64 aR[8], aZ[8], aN[8];
#pragma unroll
    for (int p = 0; p < 8; ++p) { aR[p] = 0ull; aZ[p] = 0ull; aN[p] = 0ull; }
    gemm2_tile16<32>(shf, g_WB4, j, aR, aZ, aN);
    gemm2_tile16<32>(shb, g_WC4, j, aR, aZ, aN);

    const float wdr = g_wD[j], wdz = g_wD[128 + j], wdn = g_wD[256 + j];
    const float br = bih[j], bz = bih[128 + j], bn = bih[256 + j];
    float* out = g_XGe + ((size_t)p_ * BB + b0) * GG;
#pragma unroll
    for (int p = 0; p < 8; ++p) {
        float2 r = unpack2(aR[p]);
        float2 z = unpack2(aZ[p]);
        float2 n = unpack2(aN[p]);
        {
            const int rr = 2 * p;
            const float* hg = g_HG + (size_t)shn[rr] * GG;
            float d = shd[rr];
            out[(size_t)rr * GG + j]       = r.x + hg[j]       + d * wdr + br;
            out[(size_t)rr * GG + 128 + j] = z.x + hg[128 + j] + d * wdz + bz;
            out[(size_t)rr * GG + 256 + j] = n.x + hg[256 + j] + d * wdn + bn;
        }
        {
            const int rr = 2 * p + 1;
            const float* hg = g_HG + (size_t)shn[rr] * GG;
            float d = shd[rr];
            out[(size_t)rr * GG + j]       = r.y + hg[j]       + d * wdr + br;
            out[(size_t)rr * GG + 128 + j] = z.y + hg[128 + j] + d * wdz + bz;
            out[(size_t)rr * GG + 256 + j] = n.y + hg[256 + j] + d * wdn + bn;
        }
    }
}

// ---------------- main GRU step (15 steps), fused gates ----------------
__global__ void __launch_bounds__(128) main_step_kernel(
    int t, const int* __restrict__ eids,
    const float* __restrict__ bih, const float* __restrict__ bhh,
    float* __restrict__ dout)
{
    __shared__ __align__(16) float shT[128 * ROWP];
    const int j  = threadIdx.x;
    const int b0 = blockIdx.x * 16;
    const float* hin  = (t & 1) ? g_h1 : g_h0;
    float*       hout = (t == 14) ? dout : ((t & 1) ? g_h0 : g_h1);

    float hv[16];
    {
        const float* src = hin + (size_t)b0 * OO;
#pragma unroll
        for (int i = 0; i < 16; ++i) {
            hv[i] = src[(size_t)i * 128 + j];
            shT[(size_t)j * ROWP + i] = hv[i];
        }
    }
    __syncthreads();

    u64 aR[8], aZ[8], aN[8];
#pragma unroll
    for (int p = 0; p < 8; ++p) { aR[p] = 0ull; aZ[p] = 0ull; aN[p] = 0ull; }
    gemm2_tile16<32>(shT, g_Wt4_m, j, aR, aZ, aN);

    const float cr = bhh[j], cz = bhh[128 + j], cn = bhh[256 + j];
    if ((t & 1) == 0) {
        const int p_ = t >> 1;
        const float* xg = g_XGe + ((size_t)p_ * BB + b0) * GG;
#pragma unroll
        for (int p = 0; p < 8; ++p) {
            float2 r = unpack2(aR[p]);
            float2 z = unpack2(aZ[p]);
            float2 n = unpack2(aN[p]);
#pragma unroll
            for (int s = 0; s < 2; ++s) {
                const int rr = 2 * p + s;
                const float* x = xg + (size_t)rr * GG;
                float ar = s ? r.y : r.x;
                float az = s ? z.y : z.x;
                float an = s ? n.y : n.x;
                float rg = sigf(x[j] + ar + cr);
                float zg = sigf(x[128 + j] + az + cz);
                float ng = tanhf(x[256 + j] + rg * (an + cn));
                hout[(size_t)(b0 + rr) * OO + j] = (1.f - zg) * ng + zg * hv[rr];
            }
        }
    } else {
        const int p_ = (t - 1) >> 1;
        const float br = bih[j], bz = bih[128 + j], bn = bih[256 + j];
#pragma unroll
        for (int p = 0; p < 8; ++p) {
            float2 r = unpack2(aR[p]);
            float2 z = unpack2(aZ[p]);
            float2 n = unpack2(aN[p]);
#pragma unroll
            for (int s = 0; s < 2; ++s) {
                const int rr = 2 * p + s;
                int eid = eids[(size_t)(b0 + rr) * (LL - 1) + p_];
                const float* x = g_EG + (size_t)eid * GG;
                float ar = s ? r.y : r.x;
                float az = s ? z.y : z.x;
                float an = s ? n.y : n.x;
                float rg = sigf(x[j] + br + ar + cr);
                float zg = sigf(x[128 + j] + bz + az + cz);
                float ng = tanhf(x[256 + j] + bn + rg * (an + cn));
                hout[(size_t)(b0 + rr) * OO + j] = (1.f - zg) * ng + zg * hv[rr];
            }
        }
    }
}

// ---------------------------------------------------------------------------
extern "C" void kernel_launch(void* const* d_in, const int* in_sizes, int n_in,
                              void* d_out, int out_size)
{
    (void)in_sizes; (void)n_in; (void)out_size;
    const float* h     = (const float*)d_in[0];
    const float* e     = (const float*)d_in[1];
    const float* W_e   = (const float*)d_in[2];
    const float* Wih_f = (const float*)d_in[3];
    const float* Whh_f = (const float*)d_in[4];
    const float* bih_f = (const float*)d_in[5];
    const float* bhh_f = (const float*)d_in[6];
    const float* Wih_b = (const float*)d_in[7];
    const float* Whh_b = (const float*)d_in[8];
    const float* bih_b = (const float*)d_in[9];
    const float* bhh_b = (const float*)d_in[10];
    const float* Wih   = (const float*)d_in[11];
    const float* Whh   = (const float*)d_in[12];
    const float* bih   = (const float*)d_in[13];
    const float* bhh   = (const float*)d_in[14];
    const int*   walks = (const int*)d_in[15];
    const int*   eids  = (const int*)d_in[16];
    const int*   deg   = (const int*)d_in[17];
    float* out = (float*)d_out;

    // weight packing / precombination
    transpose_w4_kernel<<<192, 256>>>(Whh_f, 128, 0,   0);
    transpose_w4_kernel<<<192, 256>>>(Whh_b, 128, 0,   1);
    transpose_w4_kernel<<<192, 256>>>(Whh,   128, 0,   2);
    transpose_w4_kernel<<<192, 256>>>(Wih,   385, 0,   3);
    transpose_w4_kernel<<<192, 256>>>(Wih,   385, 128, 4);
    transpose_w4_kernel<<<192, 256>>>(Wih,   385, 256, 5);
    wcomb_kernel<<<(GG * EFD + 255) / 256, 256>>>(Wih, W_e);
    degmax_init_kernel<<<1, 32>>>();
    degmax_kernel<<<(SS * NN * LL + 255) / 256, 256>>>(walks, deg);
    u2_kernel<<<(BB + 127) / 128, 128>>>(walks);

    // big precompute GEMMs
    gemm3_kernel<0><<<NEG / 16, 128>>>(e);            // EG [80000,384]
    gemm3_kernel<1><<<(NN + 15) / 16, 128>>>(h);      // HG [5000,384]

    // bidirectional walk GRU (8 steps, fwd+bwd fused per launch)
    dim3 wgrid(BB / 16, 2);
    for (int t = 0; t < LL; ++t)
        walk_step_kernel<<<wgrid, 128>>>(t, Wih_f, bih_f, bhh_f, Wih_b, bih_b, bhh_b);
    hwalk_kernel<<<(BB * OO + 255) / 256, 256>>>();

    // even-step input gates (one fused GEMM over all 8 walk positions)
    dim3 xg_grid(BB / 16, LL);
    xge_kernel<<<xg_grid, 128>>>(walks, deg, bih);

    // main GRU over interleaved sequence (15 steps), last step writes d_out
    for (int t = 0; t < 2 * LL - 1; ++t)
        main_step_kernel<<<BB / 16, 128>>>(t, eids, bih, bhh, out);
}

// round 13
// speedup vs baseline: 1.9471x; 1.8857x over previous
#include <cuda_runtime.h>
#include <math.h>

#define SS   4
#define NN   5000
#define LL   8
#define OO   128
#define EFD  64
#define NEG  80000
#define DIN_ 385
#define BB   20000
#define GG   384

#define NCODE 40320          // mixed-radix code space for (f_1..f_7)
#define PMAX  4224           // >= Bell(8)=4140 possible patterns

typedef unsigned long long u64;

// ---------------- device scratch (static; no allocs allowed) ----------------
__device__ __align__(16) float g_Wt4_f[32 * GG * 4];
__device__ __align__(16) float g_Wt4_b[32 * GG * 4];
__device__ __align__(16) float g_Wt4_m[32 * GG * 4];
__device__ __align__(16) float g_WA4[32 * GG * 4];
__device__ __align__(16) float g_WB4[32 * GG * 4];
__device__ __align__(16) float g_WC4[32 * GG * 4];
__device__ __align__(16) float g_Wcomb4[16 * GG * 4];
__device__ __align__(16) float g_wD[GG];
__device__ __align__(16) float g_EG[(size_t)NEG * GG];     // e @ (Wih*W_e)^T
__device__ __align__(16) float g_HG[(size_t)NN * GG];      // h @ WihA^T
__device__ __align__(16) float g_ypf[(size_t)LL * PMAX * OO];  // pattern walk fwd
__device__ __align__(16) float g_ypb[(size_t)LL * PMAX * OO];  // pattern walk bwd
__device__ __align__(16) float g_XGp[(size_t)LL * PMAX * GG];  // per-pattern even gates
__device__ __align__(16) float g_hwp[(size_t)PMAX * OO];       // per-pattern h_walk
__device__ __align__(16) float g_h0[BB * OO];
__device__ __align__(16) float g_h1[BB * OO];
__device__ int g_code[BB];
__device__ int g_pat[BB];
__device__ int g_present[NCODE];
__device__ int g_code2slot[NCODE];
__device__ int g_slot2code[PMAX];
__device__ int g_patcount;
__device__ int g_degmax;

__device__ __constant__ int FACTD[8] = {1, 1, 2, 6, 24, 120, 720, 5040};

__device__ __forceinline__ float sigf(float x) { return 1.0f / (1.0f + expf(-x)); }

// ---------------- packed f32x2 helpers (proven-passing R5 core) -------------
__device__ __forceinline__ void ffma2(u64& d, u64 a, u64 b) {
    asm("fma.rn.f32x2 %0, %1, %2, %0;" : "+l"(d) : "l"(a), "l"(b));
}
__device__ __forceinline__ u64 dup2(float w) {
    u64 r; asm("mov.b64 %0, {%1, %1};" : "=l"(r) : "f"(w)); return r;
}
__device__ __forceinline__ u64 pack2u(unsigned x, unsigned y) {
    u64 r; asm("mov.b64 %0, {%1, %2};" : "=l"(r) : "r"(x), "r"(y)); return r;
}
__device__ __forceinline__ float2 unpack2(u64 v) {
    float2 r; asm("mov.b64 {%0, %1}, %2;" : "=f"(r.x), "=f"(r.y) : "l"(v)); return r;
}

#define ROWP 20

// 16-row x 384-col GEMM tile (R5, passed at delta=0). shT[k*20+row] k-major A;
// thread j owns gate cols j, 128+j, 256+j; accumulators pack row pairs.
template <int KD4>
__device__ __forceinline__ void gemm2_tile16(
    const float* __restrict__ shT, const float* __restrict__ Wt4, int j,
    u64 (&aR)[8], u64 (&aZ)[8], u64 (&aN)[8])
{
#pragma unroll 2
    for (int k4 = 0; k4 < KD4; ++k4) {
        const float4 wa = *reinterpret_cast<const float4*>(Wt4 + ((size_t)k4 * GG + j) * 4);
        const float4 wb = *reinterpret_cast<const float4*>(Wt4 + ((size_t)k4 * GG + 128 + j) * 4);
        const float4 wc = *reinterpret_cast<const float4*>(Wt4 + ((size_t)k4 * GG + 256 + j) * 4);
        const float wfa[4] = {wa.x, wa.y, wa.z, wa.w};
        const float wfb[4] = {wb.x, wb.y, wb.z, wb.w};
        const float wfc[4] = {wc.x, wc.y, wc.z, wc.w};
#pragma unroll
        for (int kk = 0; kk < 4; ++kk) {
            const u64 dra = dup2(wfa[kk]);
            const u64 drb = dup2(wfb[kk]);
            const u64 drc = dup2(wfc[kk]);
            const uint4* ab = reinterpret_cast<const uint4*>(shT + (size_t)(k4 * 4 + kk) * ROWP);
#pragma unroll
            for (int q = 0; q < 4; ++q) {
                const uint4 v = ab[q];
                const u64 a0 = pack2u(v.x, v.y);
                const u64 a1 = pack2u(v.z, v.w);
                ffma2(aR[2 * q],     a0, dra);
                ffma2(aR[2 * q + 1], a1, dra);
                ffma2(aZ[2 * q],     a0, drb);
                ffma2(aZ[2 * q + 1], a1, drb);
                ffma2(aN[2 * q],     a0, drc);
                ffma2(aN[2 * q + 1], a1, drc);
            }
        }
    }
}

// ---------------- prep kernels ----------------
__global__ void transpose_w4_kernel(const float* __restrict__ W, int ldw, int koff, int which)
{
    int idx = blockIdx.x * 256 + threadIdx.x;
    if (idx >= GG * 128) return;
    int g = idx >> 7;
    int k = idx & 127;
    float v = W[(size_t)g * ldw + koff + k];
    float* dst = which == 0 ? g_Wt4_f : which == 1 ? g_Wt4_b : which == 2 ? g_Wt4_m
               : which == 3 ? g_WA4  : which == 4 ? g_WB4  : g_WC4;
    dst[(((size_t)(k >> 2)) * GG + g) * 4 + (k & 3)] = v;
}

__global__ void wcomb_kernel(const float* __restrict__ Wih, const float* __restrict__ We)
{
    int idx = blockIdx.x * 256 + threadIdx.x;
    if (idx >= GG * EFD) return;
    int g = idx / EFD, c = idx % EFD;
    float s = 0.f;
    for (int d = 0; d < DIN_; ++d)
        s = fmaf(Wih[(size_t)g * DIN_ + d], We[(size_t)d * EFD + c], s);
    g_Wcomb4[(((size_t)(c >> 2)) * GG + g) * 4 + (c & 3)] = s;
    if (c == 0) g_wD[g] = Wih[(size_t)g * DIN_ + (DIN_ - 1)];
}

// reset pattern tables + counters (runs every call; graph replays reuse state)
__global__ void reset_kernel()
{
    int i = blockIdx.x * 256 + threadIdx.x;
    if (i < NCODE) g_present[i] = 0;
    if (i == 0) { g_patcount = 0; g_degmax = 0; }
}

__global__ void degmax_kernel(const int* __restrict__ walks, const int* __restrict__ deg)
{
    int i = blockIdx.x * 256 + threadIdx.x;
    int v = 0;
    if (i < SS * NN * LL) v = deg[walks[i]];
    for (int off = 16; off; off >>= 1) v = max(v, __shfl_xor_sync(0xffffffffu, v, off));
    if ((threadIdx.x & 31) == 0) atomicMax(&g_degmax, v);
}

// uniqueness pattern code per walk: code = sum_t f_t * t!,  f_t = min{j<=t : w_j==w_t}
__global__ void u2code_kernel(const int* __restrict__ walks)
{
    int b = blockIdx.x * 128 + threadIdx.x;
    if (b >= BB) return;
    int w[LL];
#pragma unroll
    for (int t = 0; t < LL; ++t) w[t] = walks[(size_t)b * LL + t];
    int code = 0;
#pragma unroll
    for (int t = 1; t < LL; ++t) {
        int f = t;
#pragma unroll
        for (int jj = LL - 1; jj >= 0; --jj)
            if (jj <= t && w[jj] == w[t]) f = jj;
        code += f * FACTD[t];
    }
    g_code[b] = code;
    g_present[code] = 1;
}

__global__ void compact_kernel()
{
    int c = blockIdx.x * 256 + threadIdx.x;
    if (c >= NCODE) return;
    if (g_present[c]) {
        int slot = atomicAdd(&g_patcount, 1);
        g_slot2code[slot] = c;
        g_code2slot[c] = slot;
    }
}

__global__ void patmap_kernel()
{
    int b = blockIdx.x * 256 + threadIdx.x;
    if (b < BB) g_pat[b] = g_code2slot[g_code[b]];
}

// ---------------- big precompute GEMMs: EG (K=64) and HG (K=128) ------------
template <int MODE>   // 0: EG (A=e, W=Wcomb4, M=NEG)   1: HG (A=h, W=WA4, M=NN)
__global__ void __launch_bounds__(128) gemm3_kernel(const float* __restrict__ A)
{
    constexpr int KD4 = (MODE == 0) ? 16 : 32;
    constexpr int K   = KD4 * 4;
    const float* Wt4 = (MODE == 0) ? g_Wcomb4 : g_WA4;
    float*       C   = (MODE == 0) ? g_EG : g_HG;
    const int    M   = (MODE == 0) ? NEG : NN;

    __shared__ __align__(16) float shT[K * ROWP];
    const int j  = threadIdx.x;
    const int b0 = blockIdx.x * 16;
    for (int idx = j; idx < 16 * K; idx += 128) {
        int row = idx / K;
        int k   = idx - row * K;
        float v = (b0 + row < M) ? A[(size_t)(b0 + row) * K + k] : 0.f;
        shT[(size_t)k * ROWP + row] = v;
    }
    __syncthreads();

    u64 aR[8], aZ[8], aN[8];
#pragma unroll
    for (int p = 0; p < 8; ++p) { aR[p] = 0ull; aZ[p] = 0ull; aN[p] = 0ull; }
    gemm2_tile16<KD4>(shT, Wt4, j, aR, aZ, aN);

#pragma unroll
    for (int p = 0; p < 8; ++p) {
        float2 r = unpack2(aR[p]);
        float2 z = unpack2(aZ[p]);
        float2 n = unpack2(aN[p]);
        if (b0 + 2 * p < M) {
            float* o = C + (size_t)(b0 + 2 * p) * GG;
            o[j] = r.x; o[128 + j] = z.x; o[256 + j] = n.x;
        }
        if (b0 + 2 * p + 1 < M) {
            float* o = C + (size_t)(b0 + 2 * p + 1) * GG;
            o[j] = r.y; o[128 + j] = z.y; o[256 + j] = n.y;
        }
    }
}

// ---------------- pattern walk GRU step (fwd+bwd via grid.y) ----------------
__global__ void __launch_bounds__(128) walk_pat_kernel(
    int t,
    const float* __restrict__ Wih2_f, const float* __restrict__ bih_f,
    const float* __restrict__ bhh_f,
    const float* __restrict__ Wih2_b, const float* __restrict__ bih_b,
    const float* __restrict__ bhh_b)
{
    const int P = g_patcount;
    const int b0 = blockIdx.x * 16;
    if (b0 >= P) return;
    __shared__ __align__(16) float shT[128 * ROWP];
    __shared__ __align__(16) float shu[32];
    const int j = threadIdx.x;
    const int bwd = blockIdx.y;
    float*       ybuf = bwd ? g_ypb : g_ypf;
    const float* Wt4  = bwd ? g_Wt4_b : g_Wt4_f;
    const float* Wih2 = bwd ? Wih2_b : Wih2_f;
    const float* bih  = bwd ? bih_b : bih_f;
    const float* bhh  = bwd ? bhh_b : bhh_f;
    const int jj = bwd ? t : (LL - 1 - t);   // original f index feeding this step

    float hv[16];
    if (t > 0) {
        const float* src = ybuf + (size_t)(t - 1) * PMAX * OO + (size_t)b0 * OO;
#pragma unroll
        for (int i = 0; i < 16; ++i) {
            hv[i] = src[(size_t)i * 128 + j];
            shT[(size_t)j * ROWP + i] = hv[i];
        }
    } else {
#pragma unroll
        for (int i = 0; i < 16; ++i) hv[i] = 0.f;
    }
    if (j < 16) {
        int slot = b0 + j;
        int code = (slot < P) ? g_slot2code[slot] : 0;
        int f = (code / FACTD[jj]) % (jj + 1);
        float a = (float)f * (6.283185307179586f / (float)LL);
        shu[2 * j]     = sinf(a);
        shu[2 * j + 1] = cosf(a);
    }
    __syncthreads();

    u64 aR[8], aZ[8], aN[8];
#pragma unroll
    for (int p = 0; p < 8; ++p) { aR[p] = 0ull; aZ[p] = 0ull; aN[p] = 0ull; }
    if (t > 0) gemm2_tile16<32>(shT, Wt4, j, aR, aZ, aN);

    const float wr0 = Wih2[2 * j],         wr1 = Wih2[2 * j + 1];
    const float wz0 = Wih2[2 * (128 + j)], wz1 = Wih2[2 * (128 + j) + 1];
    const float wn0 = Wih2[2 * (256 + j)], wn1 = Wih2[2 * (256 + j) + 1];
    const float br = bih[j], bz = bih[128 + j], bn = bih[256 + j];
    const float cr = bhh[j], cz = bhh[128 + j], cn = bhh[256 + j];
    float* yo = ybuf + (size_t)t * PMAX * OO + (size_t)b0 * OO + j;
#pragma unroll
    for (int p = 0; p < 8; ++p) {
        const float4 uv = *reinterpret_cast<const float4*>(shu + 4 * p);
        float2 fR = unpack2(aR[p]);
        float2 fZ = unpack2(aZ[p]);
        float2 fN = unpack2(aN[p]);
        if (b0 + 2 * p < P) {
            float rg = sigf(fmaf(wr0, uv.x, fmaf(wr1, uv.y, br)) + fR.x + cr);
            float zg = sigf(fmaf(wz0, uv.x, fmaf(wz1, uv.y, bz)) + fZ.x + cz);
            float ng = tanhf(fmaf(wn0, uv.x, fmaf(wn1, uv.y, bn)) + rg * (fN.x + cn));
            yo[(size_t)(2 * p) * 128] = (1.f - zg) * ng + zg * hv[2 * p];
        }
        if (b0 + 2 * p + 1 < P) {
            float rg = sigf(fmaf(wr0, uv.z, fmaf(wr1, uv.w, br)) + fR.y + cr);
            float zg = sigf(fmaf(wz0, uv.z, fmaf(wz1, uv.w, bz)) + fZ.y + cz);
            float ng = tanhf(fmaf(wn0, uv.z, fmaf(wn1, uv.w, bn)) + rg * (fN.y + cn));
            yo[(size_t)(2 * p + 1) * 128] = (1.f - zg) * ng + zg * hv[2 * p + 1];
        }
    }
}

__global__ void hwalk_pat_kernel()
{
    int i = blockIdx.x * 256 + threadIdx.x;
    if (i >= PMAX * OO) return;
    if (i < g_patcount * OO)
        g_hwp[i] = 0.5f * (g_ypf[(size_t)(LL - 1) * PMAX * OO + i] +
                           g_ypb[(size_t)(LL - 1) * PMAX * OO + i]);
}

// ---------------- per-pattern even-step gates: XGp = ypf[p]@WB^T + ypb[7-p]@WC^T + bih
__global__ void __launch_bounds__(128) xge_pat_kernel(const float* __restrict__ bih)
{
    const int P = g_patcount;
    const int b0 = blockIdx.x * 16;
    if (b0 >= P) return;
    __shared__ __align__(16) float shf[128 * ROWP];
    __shared__ __align__(16) float shb[128 * ROWP];
    const int j  = threadIdx.x;
    const int p_ = blockIdx.y;

    {
        const float* f    = g_ypf + ((size_t)p_ * PMAX + b0) * OO;
        const float* bsrc = g_ypb + ((size_t)(LL - 1 - p_) * PMAX + b0) * OO;
#pragma unroll
        for (int i = 0; i < 16; ++i) {
            shf[(size_t)j * ROWP + i] = f[(size_t)i * 128 + j];
            shb[(size_t)j * ROWP + i] = bsrc[(size_t)i * 128 + j];
        }
    }
    __syncthreads();

    u64 aR[8], aZ[8], aN[8];
#pragma unroll
    for (int p = 0; p < 8; ++p) { aR[p] = 0ull; aZ[p] = 0ull; aN[p] = 0ull; }
    gemm2_tile16<32>(shf, g_WB4, j, aR, aZ, aN);
    gemm2_tile16<32>(shb, g_WC4, j, aR, aZ, aN);

    const float br = bih[j], bz = bih[128 + j], bn = bih[256 + j];
    float* out = g_XGp + ((size_t)p_ * PMAX + b0) * GG;
#pragma unroll
    for (int p = 0; p < 8; ++p) {
        float2 r = unpack2(aR[p]);
        float2 z = unpack2(aZ[p]);
        float2 n = unpack2(aN[p]);
        if (b0 + 2 * p < P) {
            float* o = out + (size_t)(2 * p) * GG;
            o[j] = r.x + br; o[128 + j] = z.x + bz; o[256 + j] = n.x + bn;
        }
        if (b0 + 2 * p + 1 < P) {
            float* o = out + (size_t)(2 * p + 1) * GG;
            o[j] = r.y + br; o[128 + j] = z.y + bz; o[256 + j] = n.y + bn;
        }
    }
}

__global__ void h0gather_kernel()
{
    int i = blockIdx.x * 256 + threadIdx.x;
    if (i >= BB * OO) return;
    int b = i >> 7, cl = i & 127;
    g_h0[i] = g_hwp[(size_t)g_pat[b] * OO + cl];
}

// ---------------- main GRU step (15 steps), fused gates ----------------
__global__ void __launch_bounds__(128) main_step_kernel(
    int t, const int* __restrict__ eids, const int* __restrict__ walks,
    const int* __restrict__ deg,
    const float* __restrict__ bih, const float* __restrict__ bhh,
    float* __restrict__ dout)
{
    __shared__ __align__(16) float shT[128 * ROWP];
    __shared__ int   sx[16];     // even: pat slot | odd: eid
    __shared__ int   snode[16];
    __shared__ float sdv[16];
    const int j  = threadIdx.x;
    const int b0 = blockIdx.x * 16;
    const float* hin  = (t & 1) ? g_h1 : g_h0;
    float*       hout = (t == 14) ? dout : ((t & 1) ? g_h0 : g_h1);
    const int even = ((t & 1) == 0);
    const int p = even ? (t >> 1) : ((t - 1) >> 1);

    float hv[16];
    {
        const float* src = hin + (size_t)b0 * OO;
#pragma unroll
        for (int i = 0; i < 16; ++i) {
            hv[i] = src[(size_t)i * 128 + j];
            shT[(size_t)j * ROWP + i] = hv[i];
        }
    }
    if (j < 16) {
        int b = b0 + j;
        if (even) {
            sx[j] = g_pat[b];
            int node = walks[(size_t)b * LL + (LL - 1 - p)];
            snode[j] = node;
            int dm = g_degmax;
            sdv[j] = (dm > 0) ? ((float)deg[node] / (float)dm) : 0.f;
        } else {
            sx[j] = eids[(size_t)b * (LL - 1) + p];
        }
    }
    __syncthreads();

    u64 aR[8], aZ[8], aN[8];
#pragma unroll
    for (int pp = 0; pp < 8; ++pp) { aR[pp] = 0ull; aZ[pp] = 0ull; aN[pp] = 0ull; }
    gemm2_tile16<32>(shT, g_Wt4_m, j, aR, aZ, aN);

    const float cr = bhh[j], cz = bhh[128 + j], cn = bhh[256 + j];
    if (even) {
        const float wdr = g_wD[j], wdz = g_wD[128 + j], wdn = g_wD[256 + j];
#pragma unroll
        for (int pp = 0; pp < 8; ++pp) {
            float2 r = unpack2(aR[pp]);
            float2 z = unpack2(aZ[pp]);
            float2 n = unpack2(aN[pp]);
#pragma unroll
            for (int s = 0; s < 2; ++s) {
                const int rr = 2 * pp + s;
                const float* x  = g_XGp + ((size_t)p * PMAX + sx[rr]) * GG;
                const float* hg = g_HG + (size_t)snode[rr] * GG;
                float d = sdv[rr];
                float ar = s ? r.y : r.x;
                float az = s ? z.y : z.x;
                float an = s ? n.y : n.x;
                float rg = sigf(x[j]       + hg[j]       + d * wdr + ar + cr);
                float zg = sigf(x[128 + j] + hg[128 + j] + d * wdz + az + cz);
                float ng = tanhf(x[256 + j] + hg[256 + j] + d * wdn + rg * (an + cn));
                hout[(size_t)(b0 + rr) * OO + j] = (1.f - zg) * ng + zg * hv[rr];
            }
        }
    } else {
        const float br = bih[j], bz = bih[128 + j], bn = bih[256 + j];
#pragma unroll
        for (int pp = 0; pp < 8; ++pp) {
            float2 r = unpack2(aR[pp]);
            float2 z = unpack2(aZ[pp]);
            float2 n = unpack2(aN[pp]);
#pragma unroll
            for (int s = 0; s < 2; ++s) {
                const int rr = 2 * pp + s;
                const float* x = g_EG + (size_t)sx[rr] * GG;
                float ar = s ? r.y : r.x;
                float az = s ? z.y : z.x;
                float an = s ? n.y : n.x;
                float rg = sigf(x[j] + br + ar + cr);
                float zg = sigf(x[128 + j] + bz + az + cz);
                float ng = tanhf(x[256 + j] + bn + rg * (an + cn));
                hout[(size_t)(b0 + rr) * OO + j] = (1.f - zg) * ng + zg * hv[rr];
            }
        }
    }
}

// ---------------------------------------------------------------------------
extern "C" void kernel_launch(void* const* d_in, const int* in_sizes, int n_in,
                              void* d_out, int out_size)
{
    (void)in_sizes; (void)n_in; (void)out_size;
    const float* h     = (const float*)d_in[0];
    const float* e     = (const float*)d_in[1];
    const float* W_e   = (const float*)d_in[2];
    const float* Wih_f = (const float*)d_in[3];
    const float* Whh_f = (const float*)d_in[4];
    const float* bih_f = (const float*)d_in[5];
    const float* bhh_f = (const float*)d_in[6];
    const float* Wih_b = (const float*)d_in[7];
    const float* Whh_b = (const float*)d_in[8];
    const float* bih_b = (const float*)d_in[9];
    const float* bhh_b = (const float*)d_in[10];
    const float* Wih   = (const float*)d_in[11];
    const float* Whh   = (const float*)d_in[12];
    const float* bih   = (const float*)d_in[13];
    const float* bhh   = (const float*)d_in[14];
    const int*   walks = (const int*)d_in[15];
    const int*   eids  = (const int*)d_in[16];
    const int*   deg   = (const int*)d_in[17];
    float* out = (float*)d_out;

    // weight packing / precombination
    transpose_w4_kernel<<<192, 256>>>(Whh_f, 128, 0,   0);
    transpose_w4_kernel<<<192, 256>>>(Whh_b, 128, 0,   1);
    transpose_w4_kernel<<<192, 256>>>(Whh,   128, 0,   2);
    transpose_w4_kernel<<<192, 256>>>(Wih,   385, 0,   3);
    transpose_w4_kernel<<<192, 256>>>(Wih,   385, 128, 4);
    transpose_w4_kernel<<<192, 256>>>(Wih,   385, 256, 5);
    wcomb_kernel<<<(GG * EFD + 255) / 256, 256>>>(Wih, W_e);

    // pattern extraction + dedup
    reset_kernel<<<(NCODE + 255) / 256, 256>>>();
    degmax_kernel<<<(SS * NN * LL + 255) / 256, 256>>>(walks, deg);
    u2code_kernel<<<(BB + 127) / 128, 128>>>(walks);
    compact_kernel<<<(NCODE + 255) / 256, 256>>>();
    patmap_kernel<<<(BB + 255) / 256, 256>>>();

    // big precompute GEMMs
    gemm3_kernel<0><<<NEG / 16, 128>>>(e);            // EG [80000,384]
    gemm3_kernel<1><<<(NN + 15) / 16, 128>>>(h);      // HG [5000,384]

    // per-pattern bidirectional walk GRU (<= 4140 patterns; blocks self-limit)
    dim3 wgrid(PMAX / 16, 2);
    for (int t = 0; t < LL; ++t)
        walk_pat_kernel<<<wgrid, 128>>>(t, Wih_f, bih_f, bhh_f, Wih_b, bih_b, bhh_b);
    hwalk_pat_kernel<<<(PMAX * OO + 255) / 256, 256>>>();

    // per-pattern even-step gates
    dim3 xg_grid(PMAX / 16, LL);
    xge_pat_kernel<<<xg_grid, 128>>>(bih);

    // h0 per walk from pattern h_walk
    h0gather_kernel<<<(BB * OO + 255) / 256, 256>>>();

    // main GRU over interleaved sequence (15 steps), last step writes d_out
    for (int t = 0; t < 2 * LL - 1; ++t)
        main_step_kernel<<<BB / 16, 128>>>(t, eids, walks, deg, bih, bhh, out);
}

// round 14
// speedup vs baseline: 2.5266x; 1.2976x over previous
#include <cuda_runtime.h>
#include <math.h>

#define SS   4
#define NN   5000
#define LL   8
#define OO   128
#define EFD  64
#define NEG  80000
#define DIN_ 385
#define BB   20000
#define GG   384

#define NCODE 40320          // mixed-radix code space for (f_1..f_7)
#define PMAX  4224           // >= Bell(8)=4140 possible patterns

typedef unsigned long long u64;

// ---------------- device scratch (static; no allocs allowed) ----------------
__device__ __align__(16) float g_Wt4_f[32 * GG * 4];
__device__ __align__(16) float g_Wt4_b[32 * GG * 4];
__device__ __align__(16) float g_Wt4_m[32 * GG * 4];
__device__ __align__(16) float g_WA4[32 * GG * 4];
__device__ __align__(16) float g_WB4[32 * GG * 4];
__device__ __align__(16) float g_WC4[32 * GG * 4];
__device__ __align__(16) float g_Wcomb4[16 * GG * 4];
__device__ __align__(16) float g_wD[GG];
__device__ __align__(16) float g_EG[(size_t)NEG * GG];     // e @ (Wih*W_e)^T
__device__ __align__(16) float g_HG[(size_t)NN * GG];      // h @ WihA^T
__device__ __align__(16) float g_ypf[(size_t)LL * PMAX * OO];  // pattern walk fwd
__device__ __align__(16) float g_ypb[(size_t)LL * PMAX * OO];  // pattern walk bwd
__device__ __align__(16) float g_XGp[(size_t)LL * PMAX * GG];  // per-pattern even gates
__device__ __align__(16) float g_hwp[(size_t)PMAX * OO];       // per-pattern h_walk
__device__ int g_code[BB];
__device__ int g_pat[BB];
__device__ int g_present[NCODE];
__device__ int g_code2slot[NCODE];
__device__ int g_slot2code[PMAX];
__device__ int g_patcount;
__device__ int g_degmax;

__device__ __constant__ int FACTD[8] = {1, 1, 2, 6, 24, 120, 720, 5040};

__device__ __forceinline__ float sigf(float x) { return 1.0f / (1.0f + expf(-x)); }

// ---------------- packed f32x2 helpers (proven-passing scalar core) ---------
__device__ __forceinline__ void ffma2(u64& d, u64 a, u64 b) {
    asm("fma.rn.f32x2 %0, %1, %2, %0;" : "+l"(d) : "l"(a), "l"(b));
}
__device__ __forceinline__ u64 dup2(float w) {
    u64 r; asm("mov.b64 %0, {%1, %1};" : "=l"(r) : "f"(w)); return r;
}
__device__ __forceinline__ u64 pack2u(unsigned x, unsigned y) {
    u64 r; asm("mov.b64 %0, {%1, %2};" : "=l"(r) : "r"(x), "r"(y)); return r;
}
__device__ __forceinline__ float2 unpack2(u64 v) {
    float2 r; asm("mov.b64 {%0, %1}, %2;" : "=f"(r.x), "=f"(r.y) : "l"(v)); return r;
}

#define ROWP 20

// 16-row x 384-col GEMM tile. shT[k*20+row] k-major A; thread j owns gate
// cols j, 128+j, 256+j; accumulators pack row pairs (2p, 2p+1).
template <int KD4>
__device__ __forceinline__ void gemm2_tile16(
    const float* __restrict__ shT, const float* __restrict__ Wt4, int j,
    u64 (&aR)[8], u64 (&aZ)[8], u64 (&aN)[8])
{
#pragma unroll 2
    for (int k4 = 0; k4 < KD4; ++k4) {
        const float4 wa = *reinterpret_cast<const float4*>(Wt4 + ((size_t)k4 * GG + j) * 4);
        const float4 wb = *reinterpret_cast<const float4*>(Wt4 + ((size_t)k4 * GG + 128 + j) * 4);
        const float4 wc = *reinterpret_cast<const float4*>(Wt4 + ((size_t)k4 * GG + 256 + j) * 4);
        const float wfa[4] = {wa.x, wa.y, wa.z, wa.w};
        const float wfb[4] = {wb.x, wb.y, wb.z, wb.w};
        const float wfc[4] = {wc.x, wc.y, wc.z, wc.w};
#pragma unroll
        for (int kk = 0; kk < 4; ++kk) {
            const u64 dra = dup2(wfa[kk]);
            const u64 drb = dup2(wfb[kk]);
            const u64 drc = dup2(wfc[kk]);
            const uint4* ab = reinterpret_cast<const uint4*>(shT + (size_t)(k4 * 4 + kk) * ROWP);
#pragma unroll
            for (int q = 0; q < 4; ++q) {
                const uint4 v = ab[q];
                const u64 a0 = pack2u(v.x, v.y);
                const u64 a1 = pack2u(v.z, v.w);
                ffma2(aR[2 * q],     a0, dra);
                ffma2(aR[2 * q + 1], a1, dra);
                ffma2(aZ[2 * q],     a0, drb);
                ffma2(aZ[2 * q + 1], a1, drb);
                ffma2(aN[2 * q],     a0, drc);
                ffma2(aN[2 * q + 1], a1, drc);
            }
        }
    }
}

// ---------------- prep kernels ----------------
__global__ void transpose_w4_kernel(const float* __restrict__ W, int ldw, int koff, int which)
{
    int idx = blockIdx.x * 256 + threadIdx.x;
    if (idx >= GG * 128) return;
    int g = idx >> 7;
    int k = idx & 127;
    float v = W[(size_t)g * ldw + koff + k];
    float* dst = which == 0 ? g_Wt4_f : which == 1 ? g_Wt4_b : which == 2 ? g_Wt4_m
               : which == 3 ? g_WA4  : which == 4 ? g_WB4  : g_WC4;
    dst[(((size_t)(k >> 2)) * GG + g) * 4 + (k & 3)] = v;
}

__global__ void wcomb_kernel(const float* __restrict__ Wih, const float* __restrict__ We)
{
    int idx = blockIdx.x * 256 + threadIdx.x;
    if (idx >= GG * EFD) return;
    int g = idx / EFD, c = idx % EFD;
    float s = 0.f;
    for (int d = 0; d < DIN_; ++d)
        s = fmaf(Wih[(size_t)g * DIN_ + d], We[(size_t)d * EFD + c], s);
    g_Wcomb4[(((size_t)(c >> 2)) * GG + g) * 4 + (c & 3)] = s;
    if (c == 0) g_wD[g] = Wih[(size_t)g * DIN_ + (DIN_ - 1)];
}

__global__ void reset_kernel()
{
    int i = blockIdx.x * 256 + threadIdx.x;
    if (i < NCODE) g_present[i] = 0;
    if (i == 0) { g_patcount = 0; g_degmax = 0; }
}

__global__ void degmax_kernel(const int* __restrict__ walks, const int* __restrict__ deg)
{
    int i = blockIdx.x * 256 + threadIdx.x;
    int v = 0;
    if (i < SS * NN * LL) v = deg[walks[i]];
    for (int off = 16; off; off >>= 1) v = max(v, __shfl_xor_sync(0xffffffffu, v, off));
    if ((threadIdx.x & 31) == 0) atomicMax(&g_degmax, v);
}

// uniqueness pattern code per walk: code = sum_t f_t * t!,  f_t = min{j<=t : w_j==w_t}
__global__ void u2code_kernel(const int* __restrict__ walks)
{
    int b = blockIdx.x * 128 + threadIdx.x;
    if (b >= BB) return;
    int w[LL];
#pragma unroll
    for (int t = 0; t < LL; ++t) w[t] = walks[(size_t)b * LL + t];
    int code = 0;
#pragma unroll
    for (int t = 1; t < LL; ++t) {
        int f = t;
#pragma unroll
        for (int jj = LL - 1; jj >= 0; --jj)
            if (jj <= t && w[jj] == w[t]) f = jj;
        code += f * FACTD[t];
    }
    g_code[b] = code;
    g_present[code] = 1;
}

__global__ void compact_kernel()
{
    int c = blockIdx.x * 256 + threadIdx.x;
    if (c >= NCODE) return;
    if (g_present[c]) {
        int slot = atomicAdd(&g_patcount, 1);
        g_slot2code[slot] = c;
        g_code2slot[c] = slot;
    }
}

__global__ void patmap_kernel()
{
    int b = blockIdx.x * 256 + threadIdx.x;
    if (b < BB) g_pat[b] = g_code2slot[g_code[b]];
}

// ---------------- big precompute GEMMs: EG (K=64) and HG (K=128) ------------
template <int MODE>   // 0: EG (A=e, W=Wcomb4, M=NEG)   1: HG (A=h, W=WA4, M=NN)
__global__ void __launch_bounds__(128) gemm3_kernel(const float* __restrict__ A)
{
    constexpr int KD4 = (MODE == 0) ? 16 : 32;
    constexpr int K   = KD4 * 4;
    const float* Wt4 = (MODE == 0) ? g_Wcomb4 : g_WA4;
    float*       C   = (MODE == 0) ? g_EG : g_HG;
    const int    M   = (MODE == 0) ? NEG : NN;

    __shared__ __align__(16) float shT[K * ROWP];
    const int j  = threadIdx.x;
    const int b0 = blockIdx.x * 16;
    for (int idx = j; idx < 16 * K; idx += 128) {
        int row = idx / K;
        int k   = idx - row * K;
        float v = (b0 + row < M) ? A[(size_t)(b0 + row) * K + k] : 0.f;
        shT[(size_t)k * ROWP + row] = v;
    }
    __syncthreads();

    u64 aR[8], aZ[8], aN[8];
#pragma unroll
    for (int p = 0; p < 8; ++p) { aR[p] = 0ull; aZ[p] = 0ull; aN[p] = 0ull; }
    gemm2_tile16<KD4>(shT, Wt4, j, aR, aZ, aN);

#pragma unroll
    for (int p = 0; p < 8; ++p) {
        float2 r = unpack2(aR[p]);
        float2 z = unpack2(aZ[p]);
        float2 n = unpack2(aN[p]);
        if (b0 + 2 * p < M) {
            float* o = C + (size_t)(b0 + 2 * p) * GG;
            o[j] = r.x; o[128 + j] = z.x; o[256 + j] = n.x;
        }
        if (b0 + 2 * p + 1 < M) {
            float* o = C + (size_t)(b0 + 2 * p + 1) * GG;
            o[j] = r.y; o[128 + j] = z.y; o[256 + j] = n.y;
        }
    }
}

// ---------------- pattern walk GRU: ALL 8 steps fused, fwd+bwd via grid.y ---
__global__ void __launch_bounds__(128) walk_fused_kernel(
    const float* __restrict__ Wih2_f, const float* __restrict__ bih_f,
    const float* __restrict__ bhh_f,
    const float* __restrict__ Wih2_b, const float* __restrict__ bih_b,
    const float* __restrict__ bhh_b)
{
    const int P = g_patcount;
    const int b0 = blockIdx.x * 16;
    if (b0 >= P) return;
    __shared__ __align__(16) float shT[128 * ROWP];
    __shared__ __align__(16) float shu[32];
    const int j = threadIdx.x;
    const int bwd = blockIdx.y;
    float*       ybuf = bwd ? g_ypb : g_ypf;
    const float* Wt4  = bwd ? g_Wt4_b : g_Wt4_f;
    const float* Wih2 = bwd ? Wih2_b : Wih2_f;
    const float* bih  = bwd ? bih_b : bih_f;
    const float* bhh  = bwd ? bhh_b : bhh_f;

    const float wr0 = Wih2[2 * j],         wr1 = Wih2[2 * j + 1];
    const float wz0 = Wih2[2 * (128 + j)], wz1 = Wih2[2 * (128 + j) + 1];
    const float wn0 = Wih2[2 * (256 + j)], wn1 = Wih2[2 * (256 + j) + 1];
    const float br = bih[j], bz = bih[128 + j], bn = bih[256 + j];
    const float cr = bhh[j], cz = bhh[128 + j], cn = bhh[256 + j];

    int mycode = 0;
    if (j < 16 && b0 + j < P) mycode = g_slot2code[b0 + j];

    float hv[16];
#pragma unroll
    for (int i = 0; i < 16; ++i) hv[i] = 0.f;

    for (int t = 0; t < LL; ++t) {
        const int jj = bwd ? t : (LL - 1 - t);   // original f index for this step
        // phase 1: publish h_prev tile + per-step u encoding
        if (t > 0) {
#pragma unroll
            for (int i = 0; i < 16; ++i) shT[(size_t)j * ROWP + i] = hv[i];
        }
        if (j < 16) {
            int f = (mycode / FACTD[jj]) % (jj + 1);
            float a = (float)f * (6.283185307179586f / (float)LL);
            shu[2 * j]     = sinf(a);
            shu[2 * j + 1] = cosf(a);
        }
        __syncthreads();

        u64 aR[8], aZ[8], aN[8];
#pragma unroll
        for (int p = 0; p < 8; ++p) { aR[p] = 0ull; aZ[p] = 0ull; aN[p] = 0ull; }
        if (t > 0) gemm2_tile16<32>(shT, Wt4, j, aR, aZ, aN);

        float* yo = ybuf + (size_t)t * PMAX * OO + (size_t)b0 * OO + j;
#pragma unroll
        for (int p = 0; p < 8; ++p) {
            const float4 uv = *reinterpret_cast<const float4*>(shu + 4 * p);
            float2 fR = unpack2(aR[p]);
            float2 fZ = unpack2(aZ[p]);
            float2 fN = unpack2(aN[p]);
            {
                float rg = sigf(fmaf(wr0, uv.x, fmaf(wr1, uv.y, br)) + fR.x + cr);
                float zg = sigf(fmaf(wz0, uv.x, fmaf(wz1, uv.y, bz)) + fZ.x + cz);
                float ng = tanhf(fmaf(wn0, uv.x, fmaf(wn1, uv.y, bn)) + rg * (fN.x + cn));
                hv[2 * p] = (1.f - zg) * ng + zg * hv[2 * p];
                if (b0 + 2 * p < P) yo[(size_t)(2 * p) * 128] = hv[2 * p];
            }
            {
                float rg = sigf(fmaf(wr0, uv.z, fmaf(wr1, uv.w, br)) + fR.y + cr);
                float zg = sigf(fmaf(wz0, uv.z, fmaf(wz1, uv.w, bz)) + fZ.y + cz);
                float ng = tanhf(fmaf(wn0, uv.z, fmaf(wn1, uv.w, bn)) + rg * (fN.y + cn));
                hv[2 * p + 1] = (1.f - zg) * ng + zg * hv[2 * p + 1];
                if (b0 + 2 * p + 1 < P) yo[(size_t)(2 * p + 1) * 128] = hv[2 * p + 1];
            }
        }
        __syncthreads();   // protect shT before next step's overwrite
    }
}

__global__ void hwalk_pat_kernel()
{
    int i = blockIdx.x * 256 + threadIdx.x;
    if (i >= PMAX * OO) return;
    if (i < g_patcount * OO)
        g_hwp[i] = 0.5f * (g_ypf[(size_t)(LL - 1) * PMAX * OO + i] +
                           g_ypb[(size_t)(LL - 1) * PMAX * OO + i]);
}

// ---------------- per-pattern even-step gates: XGp = ypf[p]@WB^T + ypb[7-p]@WC^T + bih
__global__ void __launch_bounds__(128) xge_pat_kernel(const float* __restrict__ bih)
{
    const int P = g_patcount;
    const int b0 = blockIdx.x * 16;
    if (b0 >= P) return;
    __shared__ __align__(16) float shf[128 * ROWP];
    __shared__ __align__(16) float shb[128 * ROWP];
    const int j  = threadIdx.x;
    const int p_ = blockIdx.y;

    {
        const float* f    = g_ypf + ((size_t)p_ * PMAX + b0) * OO;
        const float* bsrc = g_ypb + ((size_t)(LL - 1 - p_) * PMAX + b0) * OO;
#pragma unroll
        for (int i = 0; i < 16; ++i) {
            shf[(size_t)j * ROWP + i] = f[(size_t)i * 128 + j];
            shb[(size_t)j * ROWP + i] = bsrc[(size_t)i * 128 + j];
        }
    }
    __syncthreads();

    u64 aR[8], aZ[8], aN[8];
#pragma unroll
    for (int p = 0; p < 8; ++p) { aR[p] = 0ull; aZ[p] = 0ull; aN[p] = 0ull; }
    gemm2_tile16<32>(shf, g_WB4, j, aR, aZ, aN);
    gemm2_tile16<32>(shb, g_WC4, j, aR, aZ, aN);

    const float br = bih[j], bz = bih[128 + j], bn = bih[256 + j];
    float* out = g_XGp + ((size_t)p_ * PMAX + b0) * GG;
#pragma unroll
    for (int p = 0; p < 8; ++p) {
        float2 r = unpack2(aR[p]);
        float2 z = unpack2(aZ[p]);
        float2 n = unpack2(aN[p]);
        if (b0 + 2 * p < P) {
            float* o = out + (size_t)(2 * p) * GG;
            o[j] = r.x + br; o[128 + j] = z.x + bz; o[256 + j] = n.x + bn;
        }
        if (b0 + 2 * p + 1 < P) {
            float* o = out + (size_t)(2 * p + 1) * GG;
            o[j] = r.y + br; o[128 + j] = z.y + bz; o[256 + j] = n.y + bn;
        }
    }
}

// ---------------- main GRU: ALL 15 steps fused in one kernel ----------------
__global__ void __launch_bounds__(128) main_fused_kernel(
    const int* __restrict__ eids, const int* __restrict__ walks,
    const int* __restrict__ deg,
    const float* __restrict__ bih, const float* __restrict__ bhh,
    float* __restrict__ dout)
{
    __shared__ __align__(16) float shT[128 * ROWP];
    __shared__ int   sx[16];     // even: pat slot | odd: eid
    __shared__ int   snode[16];
    __shared__ float sdv[16];
    const int j  = threadIdx.x;
    const int b0 = blockIdx.x * 16;

    const float cr = bhh[j], cz = bhh[128 + j], cn = bhh[256 + j];
    const float br = bih[j], bz = bih[128 + j], bn = bih[256 + j];
    const float wdr = g_wD[j], wdz = g_wD[128 + j], wdn = g_wD[256 + j];

    // h0 = h_walk[pat[b]] gather (per-row)
    float hv[16];
#pragma unroll
    for (int i = 0; i < 16; ++i)
        hv[i] = g_hwp[(size_t)g_pat[b0 + i] * OO + j];

    const int dm = g_degmax;
    const float inv_dm = (dm > 0) ? (1.f / (float)dm) : 0.f;

    for (int t = 0; t < 2 * LL - 1; ++t) {
        const int even = ((t & 1) == 0);
        const int p = even ? (t >> 1) : ((t - 1) >> 1);
        // phase 1: publish h tile + per-step indices
#pragma unroll
        for (int i = 0; i < 16; ++i) shT[(size_t)j * ROWP + i] = hv[i];
        if (j < 16) {
            int b = b0 + j;
            if (even) {
                sx[j] = g_pat[b];
                int node = walks[(size_t)b * LL + (LL - 1 - p)];
                snode[j] = node;
                sdv[j] = (float)deg[node] * inv_dm;
            } else {
                sx[j] = eids[(size_t)b * (LL - 1) + p];
            }
        }
        __syncthreads();

        u64 aR[8], aZ[8], aN[8];
#pragma unroll
        for (int pp = 0; pp < 8; ++pp) { aR[pp] = 0ull; aZ[pp] = 0ull; aN[pp] = 0ull; }
        gemm2_tile16<32>(shT, g_Wt4_m, j, aR, aZ, aN);

        if (even) {
#pragma unroll
            for (int pp = 0; pp < 8; ++pp) {
                float2 r = unpack2(aR[pp]);
                float2 z = unpack2(aZ[pp]);
                float2 n = unpack2(aN[pp]);
#pragma unroll
                for (int s = 0; s < 2; ++s) {
                    const int rr = 2 * pp + s;
                    const float* x  = g_XGp + ((size_t)p * PMAX + sx[rr]) * GG;
                    const float* hg = g_HG + (size_t)snode[rr] * GG;
                    float d = sdv[rr];
                    float ar = s ? r.y : r.x;
                    float az = s ? z.y : z.x;
                    float an = s ? n.y : n.x;
                    float rg = sigf(x[j]       + hg[j]       + d * wdr + ar + cr);
                    float zg = sigf(x[128 + j] + hg[128 + j] + d * wdz + az + cz);
                    float ng = tanhf(x[256 + j] + hg[256 + j] + d * wdn + rg * (an + cn));
                    hv[rr] = (1.f - zg) * ng + zg * hv[rr];
                }
            }
        } else {
#pragma unroll
            for (int pp = 0; pp < 8; ++pp) {
                float2 r = unpack2(aR[pp]);
                float2 z = unpack2(aZ[pp]);
                float2 n = unpack2(aN[pp]);
#pragma unroll
                for (int s = 0; s < 2; ++s) {
                    const int rr = 2 * pp + s;
                    const float* x = g_EG + (size_t)sx[rr] * GG;
                    float ar = s ? r.y : r.x;
                    float az = s ? z.y : z.x;
                    float an = s ? n.y : n.x;
                    float rg = sigf(x[j] + br + ar + cr);
                    float zg = sigf(x[128 + j] + bz + az + cz);
                    float ng = tanhf(x[256 + j] + bn + rg * (an + cn));
                    hv[rr] = (1.f - zg) * ng + zg * hv[rr];
                }
            }
        }
        __syncthreads();   // shT reuse safety for next step
    }

    // write final h
#pragma unroll
    for (int i = 0; i < 16; ++i)
        dout[(size_t)(b0 + i) * OO + j] = hv[i];
}

// ---------------------------------------------------------------------------
extern "C" void kernel_launch(void* const* d_in, const int* in_sizes, int n_in,
                              void* d_out, int out_size)
{
    (void)in_sizes; (void)n_in; (void)out_size;
    const float* h     = (const float*)d_in[0];
    const float* e     = (const float*)d_in[1];
    const float* W_e   = (const float*)d_in[2];
    const float* Wih_f = (const float*)d_in[3];
    const float* Whh_f = (const float*)d_in[4];
    const float* bih_f = (const float*)d_in[5];
    const float* bhh_f = (const float*)d_in[6];
    const float* Wih_b = (const float*)d_in[7];
    const float* Whh_b = (const float*)d_in[8];
    const float* bih_b = (const float*)d_in[9];
    const float* bhh_b = (const float*)d_in[10];
    const float* Wih   = (const float*)d_in[11];
    const float* Whh   = (const float*)d_in[12];
    const float* bih   = (const float*)d_in[13];
    const float* bhh   = (const float*)d_in[14];
    const int*   walks = (const int*)d_in[15];
    const int*   eids  = (const int*)d_in[16];
    const int*   deg   = (const int*)d_in[17];
    float* out = (float*)d_out;

    // weight packing / precombination
    transpose_w4_kernel<<<192, 256>>>(Whh_f, 128, 0,   0);
    transpose_w4_kernel<<<192, 256>>>(Whh_b, 128, 0,   1);
    transpose_w4_kernel<<<192, 256>>>(Whh,   128, 0,   2);
    transpose_w4_kernel<<<192, 256>>>(Wih,   385, 0,   3);
    transpose_w4_kernel<<<192, 256>>>(Wih,   385, 128, 4);
    transpose_w4_kernel<<<192, 256>>>(Wih,   385, 256, 5);
    wcomb_kernel<<<(GG * EFD + 255) / 256, 256>>>(Wih, W_e);

    // pattern extraction + dedup
    reset_kernel<<<(NCODE + 255) / 256, 256>>>();
    degmax_kernel<<<(SS * NN * LL + 255) / 256, 256>>>(walks, deg);
    u2code_kernel<<<(BB + 127) / 128, 128>>>(walks);
    compact_kernel<<<(NCODE + 255) / 256, 256>>>();
    patmap_kernel<<<(BB + 255) / 256, 256>>>();

    // big precompute GEMMs
    gemm3_kernel<0><<<NEG / 16, 128>>>(e);            // EG [80000,384]
    gemm3_kernel<1><<<(NN + 15) / 16, 128>>>(h);      // HG [5000,384]

    // per-pattern bidirectional walk GRU: all 8 steps in one launch
    dim3 wgrid(PMAX / 16, 2);
    walk_fused_kernel<<<wgrid, 128>>>(Wih_f, bih_f, bhh_f, Wih_b, bih_b, bhh_b);
    hwalk_pat_kernel<<<(PMAX * OO + 255) / 256, 256>>>();

    // per-pattern even-step gates (all 8 positions via grid.y)
    dim3 xg_grid(PMAX / 16, LL);
    xge_pat_kernel<<<xg_grid, 128>>>(bih);

    // main GRU: all 15 steps fused; writes d_out directly
    main_fused_kernel<<<BB / 16, 128>>>(eids, walks, deg, bih, bhh, out);
}

// round 15
// speedup vs baseline: 3.3314x; 1.3185x over previous
#include <cuda_runtime.h>
#include <math.h>

#define SS   4
#define NN   5000
#define LL   8
#define OO   128
#define EFD  64
#define NEG  80000
#define DIN_ 385
#define BB   20000
#define GG   384

#define NCODE 40320          // mixed-radix code space for (f_1..f_7)
#define PMAX  4224           // >= Bell(8)=4140 possible patterns

typedef unsigned long long u64;

// ---------------- device scratch (static; no allocs allowed) ----------------
__device__ __align__(16) float g_Wt4_f[32 * GG * 4];
__device__ __align__(16) float g_Wt4_b[32 * GG * 4];
__device__ __align__(16) float g_Wt4_m[32 * GG * 4];
__device__ __align__(16) float g_WA4[32 * GG * 4];
__device__ __align__(16) float g_WB4[32 * GG * 4];
__device__ __align__(16) float g_WC4[32 * GG * 4];
__device__ __align__(16) float g_Wcomb4[16 * GG * 4];
__device__ __align__(16) float g_wD[GG];
__device__ __align__(16) float g_EG[(size_t)NEG * GG];     // e @ (Wih*W_e)^T
__device__ __align__(16) float g_HG[(size_t)NN * GG];      // h @ WihA^T
__device__ __align__(16) float g_ypf[(size_t)LL * PMAX * OO];  // pattern walk fwd
__device__ __align__(16) float g_ypb[(size_t)LL * PMAX * OO];  // pattern walk bwd
__device__ __align__(16) float g_XGp[(size_t)LL * PMAX * GG];  // per-pattern even gates
__device__ __align__(16) float g_hwp[(size_t)PMAX * OO];       // per-pattern h_walk
__device__ int g_code[BB];
__device__ int g_pat[BB];
__device__ int g_present[NCODE];
__device__ int g_code2slot[NCODE];
__device__ int g_slot2code[PMAX];
__device__ int g_patcount;
__device__ int g_degmax;

__device__ __constant__ int FACTD[8] = {1, 1, 2, 6, 24, 120, 720, 5040};

// ---------------- fast activations (MUFU-based; err ~1e-6 abs) -------------
__device__ __forceinline__ float sigf(float x) {
    float t;
    asm("ex2.approx.f32 %0, %1;" : "=f"(t) : "f"(x * -1.442695040888963f));
    float r;
    asm("rcp.approx.f32 %0, %1;" : "=f"(r) : "f"(1.0f + t));
    return r;
}
// tanh(x) = 2*sigma(2x) - 1 : absolute error ~2e-7, no tanh.approx risk
__device__ __forceinline__ float tanhf_fast(float x) {
    return fmaf(2.0f, sigf(2.0f * x), -1.0f);
}

// ---------------- packed f32x2 helpers (proven-passing scalar core) ---------
__device__ __forceinline__ void ffma2(u64& d, u64 a, u64 b) {
    asm("fma.rn.f32x2 %0, %1, %2, %0;" : "+l"(d) : "l"(a), "l"(b));
}
__device__ __forceinline__ u64 dup2(float w) {
    u64 r; asm("mov.b64 %0, {%1, %1};" : "=l"(r) : "f"(w)); return r;
}
__device__ __forceinline__ u64 pack2u(unsigned x, unsigned y) {
    u64 r; asm("mov.b64 %0, {%1, %2};" : "=l"(r) : "r"(x), "r"(y)); return r;
}
__device__ __forceinline__ float2 unpack2(u64 v) {
    float2 r; asm("mov.b64 {%0, %1}, %2;" : "=f"(r.x), "=f"(r.y) : "l"(v)); return r;
}

#define ROWP 20

// 16-row x 384-col GEMM tile. shT[k*20+row] k-major A; thread j owns gate
// cols j, 128+j, 256+j; accumulators pack row pairs (2p, 2p+1).
template <int KD4>
__device__ __forceinline__ void gemm2_tile16(
    const float* __restrict__ shT, const float* __restrict__ Wt4, int j,
    u64 (&aR)[8], u64 (&aZ)[8], u64 (&aN)[8])
{
#pragma unroll 2
    for (int k4 = 0; k4 < KD4; ++k4) {
        const float4 wa = *reinterpret_cast<const float4*>(Wt4 + ((size_t)k4 * GG + j) * 4);
        const float4 wb = *reinterpret_cast<const float4*>(Wt4 + ((size_t)k4 * GG + 128 + j) * 4);
        const float4 wc = *reinterpret_cast<const float4*>(Wt4 + ((size_t)k4 * GG + 256 + j) * 4);
        const float wfa[4] = {wa.x, wa.y, wa.z, wa.w};
        const float wfb[4] = {wb.x, wb.y, wb.z, wb.w};
        const float wfc[4] = {wc.x, wc.y, wc.z, wc.w};
#pragma unroll
        for (int kk = 0; kk < 4; ++kk) {
            const u64 dra = dup2(wfa[kk]);
            const u64 drb = dup2(wfb[kk]);
            const u64 drc = dup2(wfc[kk]);
            const uint4* ab = reinterpret_cast<const uint4*>(shT + (size_t)(k4 * 4 + kk) * ROWP);
#pragma unroll
            for (int q = 0; q < 4; ++q) {
                const uint4 v = ab[q];
                const u64 a0 = pack2u(v.x, v.y);
                const u64 a1 = pack2u(v.z, v.w);
                ffma2(aR[2 * q],     a0, dra);
                ffma2(aR[2 * q + 1], a1, dra);
                ffma2(aZ[2 * q],     a0, drb);
                ffma2(aZ[2 * q + 1], a1, drb);
                ffma2(aN[2 * q],     a0, drc);
                ffma2(aN[2 * q + 1], a1, drc);
            }
        }
    }
}

// ---------------- prep kernels ----------------
// one launch packs all 6 weight matrices: blockIdx.y selects target
__global__ void transpose_all_kernel(
    const float* __restrict__ Whh_f, const float* __restrict__ Whh_b,
    const float* __restrict__ Whh,   const float* __restrict__ Wih)
{
    int idx = blockIdx.x * 256 + threadIdx.x;
    if (idx >= GG * 128) return;
    int which = blockIdx.y;
    int g = idx >> 7;
    int k = idx & 127;
    const float* W;
    int ldw, koff;
    float* dst;
    switch (which) {
        case 0: W = Whh_f; ldw = 128; koff = 0;   dst = g_Wt4_f; break;
        case 1: W = Whh_b; ldw = 128; koff = 0;   dst = g_Wt4_b; break;
        case 2: W = Whh;   ldw = 128; koff = 0;   dst = g_Wt4_m; break;
        case 3: W = Wih;   ldw = 385; koff = 0;   dst = g_WA4;  break;
        case 4: W = Wih;   ldw = 385; koff = 128; dst = g_WB4;  break;
        default: W = Wih;  ldw = 385; koff = 256; dst = g_WC4;  break;
    }
    float v = W[(size_t)g * ldw + koff + k];
    dst[(((size_t)(k >> 2)) * GG + g) * 4 + (k & 3)] = v;
}

__global__ void wcomb_kernel(const float* __restrict__ Wih, const float* __restrict__ We)
{
    int idx = blockIdx.x * 256 + threadIdx.x;
    if (idx >= GG * EFD) return;
    int g = idx / EFD, c = idx % EFD;
    float s = 0.f;
    for (int d = 0; d < DIN_; ++d)
        s = fmaf(Wih[(size_t)g * DIN_ + d], We[(size_t)d * EFD + c], s);
    g_Wcomb4[(((size_t)(c >> 2)) * GG + g) * 4 + (c & 3)] = s;
    if (c == 0) g_wD[g] = Wih[(size_t)g * DIN_ + (DIN_ - 1)];
}

__global__ void reset_kernel()
{
    int i = blockIdx.x * 256 + threadIdx.x;
    if (i < NCODE) g_present[i] = 0;
    if (i == 0) { g_patcount = 0; g_degmax = 0; }
}

// uniqueness pattern code per walk + fused deg-max over this walk's nodes
__global__ void u2code_kernel(const int* __restrict__ walks, const int* __restrict__ deg)
{
    int b = blockIdx.x * 128 + threadIdx.x;
    if (b >= BB) return;
    int w[LL];
    int dmax = 0;
#pragma unroll
    for (int t = 0; t < LL; ++t) {
        w[t] = walks[(size_t)b * LL + t];
        dmax = max(dmax, deg[w[t]]);
    }
    int code = 0;
#pragma unroll
    for (int t = 1; t < LL; ++t) {
        int f = t;
#pragma unroll
        for (int jj = LL - 1; jj >= 0; --jj)
            if (jj <= t && w[jj] == w[t]) f = jj;
        code += f * FACTD[t];
    }
    g_code[b] = code;
    g_present[code] = 1;
    for (int off = 16; off; off >>= 1) dmax = max(dmax, __shfl_xor_sync(0xffffffffu, dmax, off));
    if ((threadIdx.x & 31) == 0) atomicMax(&g_degmax, dmax);
}

__global__ void compact_kernel()
{
    int c = blockIdx.x * 256 + threadIdx.x;
    if (c >= NCODE) return;
    if (g_present[c]) {
        int slot = atomicAdd(&g_patcount, 1);
        g_slot2code[slot] = c;
        g_code2slot[c] = slot;
    }
}

__global__ void patmap_kernel()
{
    int b = blockIdx.x * 256 + threadIdx.x;
    if (b < BB) g_pat[b] = g_code2slot[g_code[b]];
}

// ---------------- big precompute GEMMs: EG (K=64) and HG (K=128) ------------
template <int MODE>   // 0: EG (A=e, W=Wcomb4, M=NEG)   1: HG (A=h, W=WA4, M=NN)
__global__ void __launch_bounds__(128) gemm3_kernel(const float* __restrict__ A)
{
    constexpr int KD4 = (MODE == 0) ? 16 : 32;
    constexpr int K   = KD4 * 4;
    const float* Wt4 = (MODE == 0) ? g_Wcomb4 : g_WA4;
    float*       C   = (MODE == 0) ? g_EG : g_HG;
    const int    M   = (MODE == 0) ? NEG : NN;

    __shared__ __align__(16) float shT[K * ROWP];
    const int j  = threadIdx.x;
    const int b0 = blockIdx.x * 16;
    for (int idx = j; idx < 16 * K; idx += 128) {
        int row = idx / K;
        int k   = idx - row * K;
        float v = (b0 + row < M) ? A[(size_t)(b0 + row) * K + k] : 0.f;
        shT[(size_t)k * ROWP + row] = v;
    }
    __syncthreads();

    u64 aR[8], aZ[8], aN[8];
#pragma unroll
    for (int p = 0; p < 8; ++p) { aR[p] = 0ull; aZ[p] = 0ull; aN[p] = 0ull; }
    gemm2_tile16<KD4>(shT, Wt4, j, aR, aZ, aN);

#pragma unroll
    for (int p = 0; p < 8; ++p) {
        float2 r = unpack2(aR[p]);
        float2 z = unpack2(aZ[p]);
        float2 n = unpack2(aN[p]);
        if (b0 + 2 * p < M) {
            float* o = C + (size_t)(b0 + 2 * p) * GG;
            o[j] = r.x; o[128 + j] = z.x; o[256 + j] = n.x;
        }
        if (b0 + 2 * p + 1 < M) {
            float* o = C + (size_t)(b0 + 2 * p + 1) * GG;
            o[j] = r.y; o[128 + j] = z.y; o[256 + j] = n.y;
        }
    }
}

// ---------------- pattern walk GRU: ALL 8 steps fused, fwd+bwd via grid.y ---
__global__ void __launch_bounds__(128) walk_fused_kernel(
    const float* __restrict__ Wih2_f, const float* __restrict__ bih_f,
    const float* __restrict__ bhh_f,
    const float* __restrict__ Wih2_b, const float* __restrict__ bih_b,
    const float* __restrict__ bhh_b)
{
    const int P = g_patcount;
    const int b0 = blockIdx.x * 16;
    if (b0 >= P) return;
    __shared__ __align__(16) float shT[128 * ROWP];
    __shared__ __align__(16) float shu[32];
    const int j = threadIdx.x;
    const int bwd = blockIdx.y;
    float*       ybuf = bwd ? g_ypb : g_ypf;
    const float* Wt4  = bwd ? g_Wt4_b : g_Wt4_f;
    const float* Wih2 = bwd ? Wih2_b : Wih2_f;
    const float* bih  = bwd ? bih_b : bih_f;
    const float* bhh  = bwd ? bhh_b : bhh_f;

    const float wr0 = Wih2[2 * j],         wr1 = Wih2[2 * j + 1];
    const float wz0 = Wih2[2 * (128 + j)], wz1 = Wih2[2 * (128 + j) + 1];
    const float wn0 = Wih2[2 * (256 + j)], wn1 = Wih2[2 * (256 + j) + 1];
    const float br = bih[j], bz = bih[128 + j], bn = bih[256 + j];
    const float cr = bhh[j], cz = bhh[128 + j], cn = bhh[256 + j];

    int mycode = 0;
    if (j < 16 && b0 + j < P) mycode = g_slot2code[b0 + j];

    float hv[16];
#pragma unroll
    for (int i = 0; i < 16; ++i) hv[i] = 0.f;

    for (int t = 0; t < LL; ++t) {
        const int jj = bwd ? t : (LL - 1 - t);   // original f index for this step
        if (t > 0) {
#pragma unroll
            for (int i = 0; i < 16; ++i) shT[(size_t)j * ROWP + i] = hv[i];
        }
        if (j < 16) {
            int f = (mycode / FACTD[jj]) % (jj + 1);
            float a = (float)f * (6.283185307179586f / (float)LL);
            shu[2 * j]     = sinf(a);
            shu[2 * j + 1] = cosf(a);
        }
        __syncthreads();

        u64 aR[8], aZ[8], aN[8];
#pragma unroll
        for (int p = 0; p < 8; ++p) { aR[p] = 0ull; aZ[p] = 0ull; aN[p] = 0ull; }
        if (t > 0) gemm2_tile16<32>(shT, Wt4, j, aR, aZ, aN);

        float* yo = ybuf + (size_t)t * PMAX * OO + (size_t)b0 * OO + j;
#pragma unroll
        for (int p = 0; p < 8; ++p) {
            const float4 uv = *reinterpret_cast<const float4*>(shu + 4 * p);
            float2 fR = unpack2(aR[p]);
            float2 fZ = unpack2(aZ[p]);
            float2 fN = unpack2(aN[p]);
            {
                float rg = sigf(fmaf(wr0, uv.x, fmaf(wr1, uv.y, br)) + fR.x + cr);
                float zg = sigf(fmaf(wz0, uv.x, fmaf(wz1, uv.y, bz)) + fZ.x + cz);
                float ng = tanhf_fast(fmaf(wn0, uv.x, fmaf(wn1, uv.y, bn)) + rg * (fN.x + cn));
                hv[2 * p] = (1.f - zg) * ng + zg * hv[2 * p];
                if (b0 + 2 * p < P) yo[(size_t)(2 * p) * 128] = hv[2 * p];
            }
            {
                float rg = sigf(fmaf(wr0, uv.z, fmaf(wr1, uv.w, br)) + fR.y + cr);
                float zg = sigf(fmaf(wz0, uv.z, fmaf(wz1, uv.w, bz)) + fZ.y + cz);
                float ng = tanhf_fast(fmaf(wn0, uv.z, fmaf(wn1, uv.w, bn)) + rg * (fN.y + cn));
                hv[2 * p + 1] = (1.f - zg) * ng + zg * hv[2 * p + 1];
                if (b0 + 2 * p + 1 < P) yo[(size_t)(2 * p + 1) * 128] = hv[2 * p + 1];
            }
        }
        __syncthreads();   // protect shT before next step's overwrite
    }
}

__global__ void hwalk_pat_kernel()
{
    int i = blockIdx.x * 256 + threadIdx.x;
    if (i >= PMAX * OO) return;
    if (i < g_patcount * OO)
        g_hwp[i] = 0.5f * (g_ypf[(size_t)(LL - 1) * PMAX * OO + i] +
                           g_ypb[(size_t)(LL - 1) * PMAX * OO + i]);
}

// ---------------- per-pattern even-step gates: XGp = ypf[p]@WB^T + ypb[7-p]@WC^T + bih
__global__ void __launch_bounds__(128) xge_pat_kernel(const float* __restrict__ bih)
{
    const int P = g_patcount;
    const int b0 = blockIdx.x * 16;
    if (b0 >= P) return;
    __shared__ __align__(16) float shf[128 * ROWP];
    __shared__ __align__(16) float shb[128 * ROWP];
    const int j  = threadIdx.x;
    const int p_ = blockIdx.y;

    {
        const float* f    = g_ypf + ((size_t)p_ * PMAX + b0) * OO;
        const float* bsrc = g_ypb + ((size_t)(LL - 1 - p_) * PMAX + b0) * OO;
#pragma unroll
        for (int i = 0; i < 16; ++i) {
            shf[(size_t)j * ROWP + i] = f[(size_t)i * 128 + j];
            shb[(size_t)j * ROWP + i] = bsrc[(size_t)i * 128 + j];
        }
    }
    __syncthreads();

    u64 aR[8], aZ[8], aN[8];
#pragma unroll
    for (int p = 0; p < 8; ++p) { aR[p] = 0ull; aZ[p] = 0ull; aN[p] = 0ull; }
    gemm2_tile16<32>(shf, g_WB4, j, aR, aZ, aN);
    gemm2_tile16<32>(shb, g_WC4, j, aR, aZ, aN);

    const float br = bih[j], bz = bih[128 + j], bn = bih[256 + j];
    float* out = g_XGp + ((size_t)p_ * PMAX + b0) * GG;
#pragma unroll
    for (int p = 0; p < 8; ++p) {
        float2 r = unpack2(aR[p]);
        float2 z = unpack2(aZ[p]);
        float2 n = unpack2(aN[p]);
        if (b0 + 2 * p < P) {
            float* o = out + (size_t)(2 * p) * GG;
            o[j] = r.x + br; o[128 + j] = z.x + bz; o[256 + j] = n.x + bn;
        }
        if (b0 + 2 * p + 1 < P) {
            float* o = out + (size_t)(2 * p + 1) * GG;
            o[j] = r.y + br; o[128 + j] = z.y + bz; o[256 + j] = n.y + bn;
        }
    }
}

// ---------------- main GRU: ALL 15 steps fused in one kernel ----------------
__global__ void __launch_bounds__(128) main_fused_kernel(
    const int* __restrict__ eids, const int* __restrict__ walks,
    const int* __restrict__ deg,
    const float* __restrict__ bih, const float* __restrict__ bhh,
    float* __restrict__ dout)
{
    __shared__ __align__(16) float shT[128 * ROWP];
    __shared__ int   sx[16];     // even: pat slot | odd: eid
    __shared__ int   snode[16];
    __shared__ float sdv[16];
    const int j  = threadIdx.x;
    const int b0 = blockIdx.x * 16;

    const float cr = bhh[j], cz = bhh[128 + j], cn = bhh[256 + j];
    const float br = bih[j], bz = bih[128 + j], bn = bih[256 + j];
    const float wdr = g_wD[j], wdz = g_wD[128 + j], wdn = g_wD[256 + j];

    // h0 = h_walk[pat[b]] gather (per-row)
    float hv[16];
#pragma unroll
    for (int i = 0; i < 16; ++i)
        hv[i] = g_hwp[(size_t)g_pat[b0 + i] * OO + j];

    const int dm = g_degmax;
    const float inv_dm = (dm > 0) ? (1.f / (float)dm) : 0.f;

    for (int t = 0; t < 2 * LL - 1; ++t) {
        const int even = ((t & 1) == 0);
        const int p = even ? (t >> 1) : ((t - 1) >> 1);
#pragma unroll
        for (int i = 0; i < 16; ++i) shT[(size_t)j * ROWP + i] = hv[i];
        if (j < 16) {
            int b = b0 + j;
            if (even) {
                sx[j] = g_pat[b];
                int node = walks[(size_t)b * LL + (LL - 1 - p)];
                snode[j] = node;
                sdv[j] = (float)deg[node] * inv_dm;
            } else {
                sx[j] = eids[(size_t)b * (LL - 1) + p];
            }
        }
        __syncthreads();

        u64 aR[8], aZ[8], aN[8];
#pragma unroll
        for (int pp = 0; pp < 8; ++pp) { aR[pp] = 0ull; aZ[pp] = 0ull; aN[pp] = 0ull; }
        gemm2_tile16<32>(shT, g_Wt4_m, j, aR, aZ, aN);

        if (even) {
#pragma unroll
            for (int pp = 0; pp < 8; ++pp) {
                float2 r = unpack2(aR[pp]);
                float2 z = unpack2(aZ[pp]);
                float2 n = unpack2(aN[pp]);
#pragma unroll
                for (int s = 0; s < 2; ++s) {
                    const int rr = 2 * pp + s;
                    const float* x  = g_XGp + ((size_t)p * PMAX + sx[rr]) * GG;
                    const float* hg = g_HG + (size_t)snode[rr] * GG;
                    float d = sdv[rr];
                    float ar = s ? r.y : r.x;
                    float az = s ? z.y : z.x;
                    float an = s ? n.y : n.x;
                    float rg = sigf(x[j]       + hg[j]       + d * wdr + ar + cr);
                    float zg = sigf(x[128 + j] + hg[128 + j] + d * wdz + az + cz);
                    float ng = tanhf_fast(x[256 + j] + hg[256 + j] + d * wdn + rg * (an + cn));
                    hv[rr] = (1.f - zg) * ng + zg * hv[rr];
                }
            }
        } else {
#pragma unroll
            for (int pp = 0; pp < 8; ++pp) {
                float2 r = unpack2(aR[pp]);
                float2 z = unpack2(aZ[pp]);
                float2 n = unpack2(aN[pp]);
#pragma unroll
                for (int s = 0; s < 2; ++s) {
                    const int rr = 2 * pp + s;
                    const float* x = g_EG + (size_t)sx[rr] * GG;
                    float ar = s ? r.y : r.x;
                    float az = s ? z.y : z.x;
                    float an = s ? n.y : n.x;
                    float rg = sigf(x[j] + br + ar + cr);
                    float zg = sigf(x[128 + j] + bz + az + cz);
                    float ng = tanhf_fast(x[256 + j] + bn + rg * (an + cn));
                    hv[rr] = (1.f - zg) * ng + zg * hv[rr];
                }
            }
        }
        __syncthreads();   // shT reuse safety for next step
    }

    // write final h
#pragma unroll
    for (int i = 0; i < 16; ++i)
        dout[(size_t)(b0 + i) * OO + j] = hv[i];
}

// ---------------------------------------------------------------------------
extern "C" void kernel_launch(void* const* d_in, const int* in_sizes, int n_in,
                              void* d_out, int out_size)
{
    (void)in_sizes; (void)n_in; (void)out_size;
    const float* h     = (const float*)d_in[0];
    const float* e     = (const float*)d_in[1];
    const float* W_e   = (const float*)d_in[2];
    const float* Wih_f = (const float*)d_in[3];
    const float* Whh_f = (const float*)d_in[4];
    const float* bih_f = (const float*)d_in[5];
    const float* bhh_f = (const float*)d_in[6];
    const float* Wih_b = (const float*)d_in[7];
    const float* Whh_b = (const float*)d_in[8];
    const float* bih_b = (const float*)d_in[9];
    const float* bhh_b = (const float*)d_in[10];
    const float* Wih   = (const float*)d_in[11];
    const float* Whh   = (const float*)d_in[12];
    const float* bih   = (const float*)d_in[13];
    const float* bhh   = (const float*)d_in[14];
    const int*   walks = (const int*)d_in[15];
    const int*   eids  = (const int*)d_in[16];
    const int*   deg   = (const int*)d_in[17];
    float* out = (float*)d_out;

    // weight packing / precombination (one fused launch for the 6 transposes)
    dim3 tr_grid(192, 6);
    transpose_all_kernel<<<tr_grid, 256>>>(Whh_f, Whh_b, Whh, Wih);
    wcomb_kernel<<<(GG * EFD + 255) / 256, 256>>>(Wih, W_e);

    // pattern extraction + dedup (degmax fused into u2code)
    reset_kernel<<<(NCODE + 255) / 256, 256>>>();
    u2code_kernel<<<(BB + 127) / 128, 128>>>(walks, deg);
    compact_kernel<<<(NCODE + 255) / 256, 256>>>();
    patmap_kernel<<<(BB + 255) / 256, 256>>>();

    // big precompute GEMMs
    gemm3_kernel<0><<<NEG / 16, 128>>>(e);            // EG [80000,384]
    gemm3_kernel<1><<<(NN + 15) / 16, 128>>>(h);      // HG [5000,384]

    // per-pattern bidirectional walk GRU: all 8 steps in one launch
    dim3 wgrid(PMAX / 16, 2);
    walk_fused_kernel<<<wgrid, 128>>>(Wih_f, bih_f, bhh_f, Wih_b, bih_b, bhh_b);
    hwalk_pat_kernel<<<(PMAX * OO + 255) / 256, 256>>>();

    // per-pattern even-step gates (all 8 positions via grid.y)
    dim3 xg_grid(PMAX / 16, LL);
    xge_pat_kernel<<<xg_grid, 128>>>(bih);

    // main GRU: all 15 steps fused; writes d_out directly
    main_fused_kernel<<<BB / 16, 128>>>(eids, walks, deg, bih, bhh, out);
}

// round 16
// speedup vs baseline: 3.4157x; 1.0253x over previous
#include <cuda_runtime.h>
#include <cuda_fp16.h>
#include <math.h>

#define SS   4
#define NN   5000
#define LL   8
#define OO   128
#define EFD  64
#define NEG  80000
#define DIN_ 385
#define BB   20000
#define GG   384

#define NCODE 40320          // mixed-radix code space for (f_1..f_7)
#define PMAX  4224           // >= Bell(8)=4140 possible patterns

typedef unsigned long long u64;

// ---------------- device scratch (static; no allocs allowed) ----------------
__device__ __align__(16) float g_Wt4_f[32 * GG * 4];
__device__ __align__(16) float g_Wt4_b[32 * GG * 4];
__device__ __align__(16) float g_Wt4_m[32 * GG * 4];
__device__ __align__(16) float g_WA4[32 * GG * 4];
__device__ __align__(16) float g_WB4[32 * GG * 4];
__device__ __align__(16) float g_WC4[32 * GG * 4];
__device__ __align__(16) float g_Wcomb[GG * EFD];        // plain [384][64]
__device__ __align__(16) unsigned g_BpkHi[48 * 4 * 32 * 2];  // fp16 frag-packed Wcomb hi
__device__ __align__(16) unsigned g_BpkLo[48 * 4 * 32 * 2];  // fp16 frag-packed Wcomb lo
__device__ __align__(16) float g_wD[GG];
__device__ __align__(16) float g_EG[(size_t)NEG * GG];     // e @ (Wih*W_e)^T
__device__ __align__(16) float g_HG[(size_t)NN * GG];      // h @ WihA^T
__device__ __align__(16) float g_ypf[(size_t)LL * PMAX * OO];  // pattern walk fwd
__device__ __align__(16) float g_ypb[(size_t)LL * PMAX * OO];  // pattern walk bwd
__device__ __align__(16) float g_XGp[(size_t)LL * PMAX * GG];  // per-pattern even gates
__device__ __align__(16) float g_hwp[(size_t)PMAX * OO];       // per-pattern h_walk
__device__ int g_code[BB];
__device__ int g_pat[BB];
__device__ int g_present[NCODE];
__device__ int g_code2slot[NCODE];
__device__ int g_slot2code[PMAX];
__device__ int g_patcount;
__device__ int g_degmax;

__device__ __constant__ int FACTD[8] = {1, 1, 2, 6, 24, 120, 720, 5040};

// ---------------- fast activations (MUFU-based; err ~1e-6 abs) -------------
__device__ __forceinline__ float sigf(float x) {
    float t;
    asm("ex2.approx.f32 %0, %1;" : "=f"(t) : "f"(x * -1.442695040888963f));
    float r;
    asm("rcp.approx.f32 %0, %1;" : "=f"(r) : "f"(1.0f + t));
    return r;
}
// tanh(x) = 2*sigma(2x) - 1 : absolute error ~2e-7
__device__ __forceinline__ float tanhf_fast(float x) {
    return fmaf(2.0f, sigf(2.0f * x), -1.0f);
}

// ---------------- packed f32x2 helpers (proven-passing scalar core) ---------
__device__ __forceinline__ void ffma2(u64& d, u64 a, u64 b) {
    asm("fma.rn.f32x2 %0, %1, %2, %0;" : "+l"(d) : "l"(a), "l"(b));
}
__device__ __forceinline__ u64 dup2(float w) {
    u64 r; asm("mov.b64 %0, {%1, %1};" : "=l"(r) : "f"(w)); return r;
}
__device__ __forceinline__ u64 pack2u(unsigned x, unsigned y) {
    u64 r; asm("mov.b64 %0, {%1, %2};" : "=l"(r) : "r"(x), "r"(y)); return r;
}
__device__ __forceinline__ float2 unpack2(u64 v) {
    float2 r; asm("mov.b64 {%0, %1}, %2;" : "=f"(r.x), "=f"(r.y) : "l"(v)); return r;
}

#define ROWP 20

// 16-row x 384-col GEMM tile. shT[k*20+row] k-major A; thread j owns gate
// cols j, 128+j, 256+j; accumulators pack row pairs (2p, 2p+1).
template <int KD4>
__device__ __forceinline__ void gemm2_tile16(
    const float* __restrict__ shT, const float* __restrict__ Wt4, int j,
    u64 (&aR)[8], u64 (&aZ)[8], u64 (&aN)[8])
{
#pragma unroll 2
    for (int k4 = 0; k4 < KD4; ++k4) {
        const float4 wa = *reinterpret_cast<const float4*>(Wt4 + ((size_t)k4 * GG + j) * 4);
        const float4 wb = *reinterpret_cast<const float4*>(Wt4 + ((size_t)k4 * GG + 128 + j) * 4);
        const float4 wc = *reinterpret_cast<const float4*>(Wt4 + ((size_t)k4 * GG + 256 + j) * 4);
        const float wfa[4] = {wa.x, wa.y, wa.z, wa.w};
        const float wfb[4] = {wb.x, wb.y, wb.z, wb.w};
        const float wfc[4] = {wc.x, wc.y, wc.z, wc.w};
#pragma unroll
        for (int kk = 0; kk < 4; ++kk) {
            const u64 dra = dup2(wfa[kk]);
            const u64 drb = dup2(wfb[kk]);
            const u64 drc = dup2(wfc[kk]);
            const uint4* ab = reinterpret_cast<const uint4*>(shT + (size_t)(k4 * 4 + kk) * ROWP);
#pragma unroll
            for (int q = 0; q < 4; ++q) {
                const uint4 v = ab[q];
                const u64 a0 = pack2u(v.x, v.y);
                const u64 a1 = pack2u(v.z, v.w);
                ffma2(aR[2 * q],     a0, dra);
                ffma2(aR[2 * q + 1], a1, dra);
                ffma2(aZ[2 * q],     a0, drb);
                ffma2(aZ[2 * q + 1], a1, drb);
                ffma2(aN[2 * q],     a0, drc);
                ffma2(aN[2 * q + 1], a1, drc);
            }
        }
    }
}

// ---------------- prep kernels ----------------
__global__ void transpose_all_kernel(
    const float* __restrict__ Whh_f, const float* __restrict__ Whh_b,
    const float* __restrict__ Whh,   const float* __restrict__ Wih)
{
    int idx = blockIdx.x * 256 + threadIdx.x;
    if (idx >= GG * 128) return;
    int which = blockIdx.y;
    int g = idx >> 7;
    int k = idx & 127;
    const float* W;
    int ldw, koff;
    float* dst;
    switch (which) {
        case 0: W = Whh_f; ldw = 128; koff = 0;   dst = g_Wt4_f; break;
        case 1: W = Whh_b; ldw = 128; koff = 0;   dst = g_Wt4_b; break;
        case 2: W = Whh;   ldw = 128; koff = 0;   dst = g_Wt4_m; break;
        case 3: W = Wih;   ldw = 385; koff = 0;   dst = g_WA4;  break;
        case 4: W = Wih;   ldw = 385; koff = 128; dst = g_WB4;  break;
        default: W = Wih;  ldw = 385; koff = 256; dst = g_WC4;  break;
    }
    float v = W[(size_t)g * ldw + koff + k];
    dst[(((size_t)(k >> 2)) * GG + g) * 4 + (k & 3)] = v;
}

__global__ void wcomb_kernel(const float* __restrict__ Wih, const float* __restrict__ We)
{
    int idx = blockIdx.x * 256 + threadIdx.x;
    if (idx >= GG * EFD) return;
    int g = idx / EFD, c = idx % EFD;
    float s = 0.f;
    for (int d = 0; d < DIN_; ++d)
        s = fmaf(Wih[(size_t)g * DIN_ + d], We[(size_t)d * EFD + c], s);
    g_Wcomb[(size_t)g * EFD + c] = s;
    if (c == 0) g_wD[g] = Wih[(size_t)g * DIN_ + (DIN_ - 1)];
}

// pack Wcomb into fp16 hi/lo mma B-fragments: [ntile][kstep][lane][2] uints
__global__ void bpack_kernel()
{
    int idx = blockIdx.x * 256 + threadIdx.x;
    if (idx >= 48 * 4 * 32 * 2) return;
    int rp    = idx & 1;
    int lane  = (idx >> 1) & 31;
    int ks    = (idx >> 6) & 3;
    int ntile = idx >> 8;
    int n = ntile * 8 + (lane >> 2);
    int k = ks * 16 + (lane & 3) * 2 + rp * 8;
    float x0 = g_Wcomb[(size_t)n * EFD + k];
    float x1 = g_Wcomb[(size_t)n * EFD + k + 1];
    __half h0 = __float2half_rn(x0), h1 = __float2half_rn(x1);
    g_BpkHi[idx] = (unsigned)__half_as_ushort(h0) | ((unsigned)__half_as_ushort(h1) << 16);
    __half l0 = __float2half_rn(x0 - __half2float(h0));
    __half l1 = __float2half_rn(x1 - __half2float(h1));
    g_BpkLo[idx] = (unsigned)__half_as_ushort(l0) | ((unsigned)__half_as_ushort(l1) << 16);
}

__global__ void reset_kernel()
{
    int i = blockIdx.x * 256 + threadIdx.x;
    if (i < NCODE) g_present[i] = 0;
    if (i == 0) { g_patcount = 0; g_degmax = 0; }
}

__global__ void u2code_kernel(const int* __restrict__ walks, const int* __restrict__ deg)
{
    int b = blockIdx.x * 128 + threadIdx.x;
    if (b >= BB) return;
    int w[LL];
    int dmax = 0;
#pragma unroll
    for (int t = 0; t < LL; ++t) {
        w[t] = walks[(size_t)b * LL + t];
        dmax = max(dmax, deg[w[t]]);
    }
    int code = 0;
#pragma unroll
    for (int t = 1; t < LL; ++t) {
        int f = t;
#pragma unroll
        for (int jj = LL - 1; jj >= 0; --jj)
            if (jj <= t && w[jj] == w[t]) f = jj;
        code += f * FACTD[t];
    }
    g_code[b] = code;
    g_present[code] = 1;
    for (int off = 16; off; off >>= 1) dmax = max(dmax, __shfl_xor_sync(0xffffffffu, dmax, off));
    if ((threadIdx.x & 31) == 0) atomicMax(&g_degmax, dmax);
}

__global__ void compact_kernel()
{
    int c = blockIdx.x * 256 + threadIdx.x;
    if (c >= NCODE) return;
    if (g_present[c]) {
        int slot = atomicAdd(&g_patcount, 1);
        g_slot2code[slot] = c;
        g_code2slot[c] = slot;
    }
}

__global__ void patmap_kernel()
{
    int b = blockIdx.x * 256 + threadIdx.x;
    if (b < BB) g_pat[b] = g_code2slot[g_code[b]];
}

// ---------------- EG via fp16 split mma (m16n8k16, f32 accumulate) ----------
// block = 16 e-rows; 4 warps x 12 n8-tiles = 384 cols. C: hi*hi + hi*lo + lo*hi.
#define H2PK(h0v, h1v) ((unsigned)__half_as_ushort(h0v) | ((unsigned)__half_as_ushort(h1v) << 16))

#define MMA16816(Cv, A0, A1, A2, A3, B0, B1)                                \
    asm volatile(                                                           \
        "mma.sync.aligned.m16n8k16.row.col.f32.f16.f16.f32 "                \
        "{%0,%1,%2,%3},{%4,%5,%6,%7},{%8,%9},{%0,%1,%2,%3};"                \
        : "+f"(Cv[0]), "+f"(Cv[1]), "+f"(Cv[2]), "+f"(Cv[3])                \
        : "r"(A0), "r"(A1), "r"(A2), "r"(A3), "r"(B0), "r"(B1))

__global__ void __launch_bounds__(128) eg_mma_kernel(const float* __restrict__ e)
{
    __shared__ __align__(16) float sE[16 * 68];
    const int tid = threadIdx.x;
    const int b0 = blockIdx.x * 16;
    for (int i = tid; i < 16 * 16; i += 128) {
        int r = i >> 4, c4 = i & 15;
        float4 v = *reinterpret_cast<const float4*>(e + (size_t)(b0 + r) * EFD + c4 * 4);
        *reinterpret_cast<float4*>(sE + r * 68 + c4 * 4) = v;
    }
    __syncthreads();

    const int w = tid >> 5, lane = tid & 31;
    const int g = lane >> 2, tg = lane & 3;

    float C[12][4];
#pragma unroll
    for (int nt = 0; nt < 12; ++nt)
#pragma unroll
        for (int q = 0; q < 4; ++q) C[nt][q] = 0.f;

#pragma unroll
    for (int ks = 0; ks < 4; ++ks) {
        const int c0 = ks * 16 + tg * 2;
        // A rows g and g+8, cols c0,c0+1,c0+8,c0+9
        float x00 = sE[g * 68 + c0],     x01 = sE[g * 68 + c0 + 1];
        float x08 = sE[g * 68 + c0 + 8], x09 = sE[g * 68 + c0 + 9];
        float x10 = sE[(g + 8) * 68 + c0],     x11 = sE[(g + 8) * 68 + c0 + 1];
        float x18 = sE[(g + 8) * 68 + c0 + 8], x19 = sE[(g + 8) * 68 + c0 + 9];
        __half h00 = __float2half_rn(x00), h01 = __float2half_rn(x01);
        __half h08 = __float2half_rn(x08), h09 = __float2half_rn(x09);
        __half h10 = __float2half_rn(x10), h11 = __float2half_rn(x11);
        __half h18 = __float2half_rn(x18), h19 = __float2half_rn(x19);
        unsigned ah0 = H2PK(h00, h01), ah1 = H2PK(h10, h11);
        unsigned ah2 = H2PK(h08, h09), ah3 = H2PK(h18, h19);
        __half l00 = __float2half_rn(x00 - __half2float(h00));
        __half l01 = __float2half_rn(x01 - __half2float(h01));
        __half l08 = __float2half_rn(x08 - __half2float(h08));
        __half l09 = __float2half_rn(x09 - __half2float(h09));
        __half l10 = __float2half_rn(x10 - __half2float(h10));
        __half l11 = __float2half_rn(x11 - __half2float(h11));
        __half l18 = __float2half_rn(x18 - __half2float(h18));
        __half l19 = __float2half_rn(x19 - __half2float(h19));
        unsigned al0 = H2PK(l00, l01), al1 = H2PK(l10, l11);
        unsigned al2 = H2PK(l08, l09), al3 = H2PK(l18, l19);
#pragma unroll
        for (int nt = 0; nt < 12; ++nt) {
            const int ntile = w * 12 + nt;
            const uint2 bh = *reinterpret_cast<const uint2*>(
                g_BpkHi + ((size_t)(ntile * 4 + ks) * 32 + lane) * 2);
            const uint2 bl = *reinterpret_cast<const uint2*>(
                g_BpkLo + ((size_t)(ntile * 4 + ks) * 32 + lane) * 2);
            MMA16816(C[nt], ah0, ah1, ah2, ah3, bh.x, bh.y);
            MMA16816(C[nt], ah0, ah1, ah2, ah3, bl.x, bl.y);
            MMA16816(C[nt], al0, al1, al2, al3, bh.x, bh.y);
        }
    }

#pragma unroll
    for (int nt = 0; nt < 12; ++nt) {
        const int col = (w * 12 + nt) * 8 + tg * 2;
        *reinterpret_cast<float2*>(g_EG + (size_t)(b0 + g) * GG + col) =
            make_float2(C[nt][0], C[nt][1]);
        *reinterpret_cast<float2*>(g_EG + (size_t)(b0 + g + 8) * GG + col) =
            make_float2(C[nt][2], C[nt][3]);
    }
}

// ---------------- HG GEMM (K=128, scalar core, unchanged) -------------------
__global__ void __launch_bounds__(128) gemm3_hg_kernel(const float* __restrict__ A)
{
    constexpr int KD4 = 32;
    constexpr int K   = 128;
    const int    M    = NN;
    __shared__ __align__(16) float shT[K * ROWP];
    const int j  = threadIdx.x;
    const int b0 = blockIdx.x * 16;
    for (int idx = j; idx < 16 * K; idx += 128) {
        int row = idx / K;
        int k   = idx - row * K;
        float v = (b0 + row < M) ? A[(size_t)(b0 + row) * K + k] : 0.f;
        shT[(size_t)k * ROWP + row] = v;
    }
    __syncthreads();

    u64 aR[8], aZ[8], aN[8];
#pragma unroll
    for (int p = 0; p < 8; ++p) { aR[p] = 0ull; aZ[p] = 0ull; aN[p] = 0ull; }
    gemm2_tile16<KD4>(shT, g_WA4, j, aR, aZ, aN);

#pragma unroll
    for (int p = 0; p < 8; ++p) {
        float2 r = unpack2(aR[p]);
        float2 z = unpack2(aZ[p]);
        float2 n = unpack2(aN[p]);
        if (b0 + 2 * p < M) {
            float* o = g_HG + (size_t)(b0 + 2 * p) * GG;
            o[j] = r.x; o[128 + j] = z.x; o[256 + j] = n.x;
        }
        if (b0 + 2 * p + 1 < M) {
            float* o = g_HG + (size_t)(b0 + 2 * p + 1) * GG;
            o[j] = r.y; o[128 + j] = z.y; o[256 + j] = n.y;
        }
    }
}

// ---------------- pattern walk GRU: ALL 8 steps fused, fwd+bwd via grid.y ---
__global__ void __launch_bounds__(128) walk_fused_kernel(
    const float* __restrict__ Wih2_f, const float* __restrict__ bih_f,
    const float* __restrict__ bhh_f,
    const float* __restrict__ Wih2_b, const float* __restrict__ bih_b,
    const float* __restrict__ bhh_b)
{
    const int P = g_patcount;
    const int b0 = blockIdx.x * 16;
    if (b0 >= P) return;
    __shared__ __align__(16) float shT[128 * ROWP];
    __shared__ __align__(16) float shu[32];
    const int j = threadIdx.x;
    const int bwd = blockIdx.y;
    float*       ybuf = bwd ? g_ypb : g_ypf;
    const float* Wt4  = bwd ? g_Wt4_b : g_Wt4_f;
    const float* Wih2 = bwd ? Wih2_b : Wih2_f;
    const float* bih  = bwd ? bih_b : bih_f;
    const float* bhh  = bwd ? bhh_b : bhh_f;

    const float wr0 = Wih2[2 * j],         wr1 = Wih2[2 * j + 1];
    const float wz0 = Wih2[2 * (128 + j)], wz1 = Wih2[2 * (128 + j) + 1];
    const float wn0 = Wih2[2 * (256 + j)], wn1 = Wih2[2 * (256 + j) + 1];
    const float br = bih[j], bz = bih[128 + j], bn = bih[256 + j];
    const float cr = bhh[j], cz = bhh[128 + j], cn = bhh[256 + j];

    int mycode = 0;
    if (j < 16 && b0 + j < P) mycode = g_slot2code[b0 + j];

    float hv[16];
#pragma unroll
    for (int i = 0; i < 16; ++i) hv[i] = 0.f;

    for (int t = 0; t < LL; ++t) {
        const int jj = bwd ? t : (LL - 1 - t);
        if (t > 0) {
#pragma unroll
            for (int i = 0; i < 16; ++i) shT[(size_t)j * ROWP + i] = hv[i];
        }
        if (j < 16) {
            int f = (mycode / FACTD[jj]) % (jj + 1);
            float a = (float)f * (6.283185307179586f / (float)LL);
            shu[2 * j]     = sinf(a);
            shu[2 * j + 1] = cosf(a);
        }
        __syncthreads();

        u64 aR[8], aZ[8], aN[8];
#pragma unroll
        for (int p = 0; p < 8; ++p) { aR[p] = 0ull; aZ[p] = 0ull; aN[p] = 0ull; }
        if (t > 0) gemm2_tile16<32>(shT, Wt4, j, aR, aZ, aN);

        float* yo = ybuf + (size_t)t * PMAX * OO + (size_t)b0 * OO + j;
#pragma unroll
        for (int p = 0; p < 8; ++p) {
            const float4 uv = *reinterpret_cast<const float4*>(shu + 4 * p);
            float2 fR = unpack2(aR[p]);
            float2 fZ = unpack2(aZ[p]);
            float2 fN = unpack2(aN[p]);
            {
                float rg = sigf(fmaf(wr0, uv.x, fmaf(wr1, uv.y, br)) + fR.x + cr);
                float zg = sigf(fmaf(wz0, uv.x, fmaf(wz1, uv.y, bz)) + fZ.x + cz);
                float ng = tanhf_fast(fmaf(wn0, uv.x, fmaf(wn1, uv.y, bn)) + rg * (fN.x + cn));
                hv[2 * p] = (1.f - zg) * ng + zg * hv[2 * p];
                if (b0 + 2 * p < P) yo[(size_t)(2 * p) * 128] = hv[2 * p];
            }
            {
                float rg = sigf(fmaf(wr0, uv.z, fmaf(wr1, uv.w, br)) + fR.y + cr);
                float zg = sigf(fmaf(wz0, uv.z, fmaf(wz1, uv.w, bz)) + fZ.y + cz);
                float ng = tanhf_fast(fmaf(wn0, uv.z, fmaf(wn1, uv.w, bn)) + rg * (fN.y + cn));
                hv[2 * p + 1] = (1.f - zg) * ng + zg * hv[2 * p + 1];
                if (b0 + 2 * p + 1 < P) yo[(size_t)(2 * p + 1) * 128] = hv[2 * p + 1];
            }
        }
        __syncthreads();
    }
}

__global__ void hwalk_pat_kernel()
{
    int i = blockIdx.x * 256 + threadIdx.x;
    if (i >= PMAX * OO) return;
    if (i < g_patcount * OO)
        g_hwp[i] = 0.5f * (g_ypf[(size_t)(LL - 1) * PMAX * OO + i] +
                           g_ypb[(size_t)(LL - 1) * PMAX * OO + i]);
}

// ---------------- per-pattern even-step gates -------------------------------
__global__ void __launch_bounds__(128) xge_pat_kernel(const float* __restrict__ bih)
{
    const int P = g_patcount;
    const int b0 = blockIdx.x * 16;
    if (b0 >= P) return;
    __shared__ __align__(16) float shf[128 * ROWP];
    __shared__ __align__(16) float shb[128 * ROWP];
    const int j  = threadIdx.x;
    const int p_ = blockIdx.y;

    {
        const float* f    = g_ypf + ((size_t)p_ * PMAX + b0) * OO;
        const float* bsrc = g_ypb + ((size_t)(LL - 1 - p_) * PMAX + b0) * OO;
#pragma unroll
        for (int i = 0; i < 16; ++i) {
            shf[(size_t)j * ROWP + i] = f[(size_t)i * 128 + j];
            shb[(size_t)j * ROWP + i] = bsrc[(size_t)i * 128 + j];
        }
    }
    __syncthreads();

    u64 aR[8], aZ[8], aN[8];
#pragma unroll
    for (int p = 0; p < 8; ++p) { aR[p] = 0ull; aZ[p] = 0ull; aN[p] = 0ull; }
    gemm2_tile16<32>(shf, g_WB4, j, aR, aZ, aN);
    gemm2_tile16<32>(shb, g_WC4, j, aR, aZ, aN);

    const float br = bih[j], bz = bih[128 + j], bn = bih[256 + j];
    float* out = g_XGp + ((size_t)p_ * PMAX + b0) * GG;
#pragma unroll
    for (int p = 0; p < 8; ++p) {
        float2 r = unpack2(aR[p]);
        float2 z = unpack2(aZ[p]);
        float2 n = unpack2(aN[p]);
        if (b0 + 2 * p < P) {
            float* o = out + (size_t)(2 * p) * GG;
            o[j] = r.x + br; o[128 + j] = z.x + bz; o[256 + j] = n.x + bn;
        }
        if (b0 + 2 * p + 1 < P) {
            float* o = out + (size_t)(2 * p + 1) * GG;
            o[j] = r.y + br; o[128 + j] = z.y + bz; o[256 + j] = n.y + bn;
        }
    }
}

// ---------------- main GRU: ALL 15 steps fused in one kernel ----------------
__global__ void __launch_bounds__(128) main_fused_kernel(
    const int* __restrict__ eids, const int* __restrict__ walks,
    const int* __restrict__ deg,
    const float* __restrict__ bih, const float* __restrict__ bhh,
    float* __restrict__ dout)
{
    __shared__ __align__(16) float shT[128 * ROWP];
    __shared__ int   sx[16];
    __shared__ int   snode[16];
    __shared__ float sdv[16];
    const int j  = threadIdx.x;
    const int b0 = blockIdx.x * 16;

    const float cr = bhh[j], cz = bhh[128 + j], cn = bhh[256 + j];
    const float br = bih[j], bz = bih[128 + j], bn = bih[256 + j];
    const float wdr = g_wD[j], wdz = g_wD[128 + j], wdn = g_wD[256 + j];

    float hv[16];
#pragma unroll
    for (int i = 0; i < 16; ++i)
        hv[i] = g_hwp[(size_t)g_pat[b0 + i] * OO + j];

    const int dm = g_degmax;
    const float inv_dm = (dm > 0) ? (1.f / (float)dm) : 0.f;

    for (int t = 0; t < 2 * LL - 1; ++t) {
        const int even = ((t & 1) == 0);
        const int p = even ? (t >> 1) : ((t - 1) >> 1);
#pragma unroll
        for (int i = 0; i < 16; ++i) shT[(size_t)j * ROWP + i] = hv[i];
        if (j < 16) {
            int b = b0 + j;
            if (even) {
                sx[j] = g_pat[b];
                int node = walks[(size_t)b * LL + (LL - 1 - p)];
                snode[j] = node;
                sdv[j] = (float)deg[node] * inv_dm;
            } else {
                sx[j] = eids[(size_t)b * (LL - 1) + p];
            }
        }
        __syncthreads();

        u64 aR[8], aZ[8], aN[8];
#pragma unroll
        for (int pp = 0; pp < 8; ++pp) { aR[pp] = 0ull; aZ[pp] = 0ull; aN[pp] = 0ull; }
        gemm2_tile16<32>(shT, g_Wt4_m, j, aR, aZ, aN);

        if (even) {
#pragma unroll
            for (int pp = 0; pp < 8; ++pp) {
                float2 r = unpack2(aR[pp]);
                float2 z = unpack2(aZ[pp]);
                float2 n = unpack2(aN[pp]);
#pragma unroll
                for (int s = 0; s < 2; ++s) {
                    const int rr = 2 * pp + s;
                    const float* x  = g_XGp + ((size_t)p * PMAX + sx[rr]) * GG;
                    const float* hg = g_HG + (size_t)snode[rr] * GG;
                    float d = sdv[rr];
                    float ar = s ? r.y : r.x;
                    float az = s ? z.y : z.x;
                    float an = s ? n.y : n.x;
                    float rg = sigf(x[j]       + hg[j]       + d * wdr + ar + cr);
                    float zg = sigf(x[128 + j] + hg[128 + j] + d * wdz + az + cz);
                    float ng = tanhf_fast(x[256 + j] + hg[256 + j] + d * wdn + rg * (an + cn));
                    hv[rr] = (1.f - zg) * ng + zg * hv[rr];
                }
            }
        } else {
#pragma unroll
            for (int pp = 0; pp < 8; ++pp) {
                float2 r = unpack2(aR[pp]);
                float2 z = unpack2(aZ[pp]);
                float2 n = unpack2(aN[pp]);
#pragma unroll
                for (int s = 0; s < 2; ++s) {
                    const int rr = 2 * pp + s;
                    const float* x = g_EG + (size_t)sx[rr] * GG;
                    float ar = s ? r.y : r.x;
                    float az = s ? z.y : z.x;
                    float an = s ? n.y : n.x;
                    float rg = sigf(x[j] + br + ar + cr);
                    float zg = sigf(x[128 + j] + bz + az + cz);
                    float ng = tanhf_fast(x[256 + j] + bn + rg * (an + cn));
                    hv[rr] = (1.f - zg) * ng + zg * hv[rr];
                }
            }
        }
        __syncthreads();
    }

#pragma unroll
    for (int i = 0; i < 16; ++i)
        dout[(size_t)(b0 + i) * OO + j] = hv[i];
}

// ---------------------------------------------------------------------------
extern "C" void kernel_launch(void* const* d_in, const int* in_sizes, int n_in,
                              void* d_out, int out_size)
{
    (void)in_sizes; (void)n_in; (void)out_size;
    const float* h     = (const float*)d_in[0];
    const float* e     = (const float*)d_in[1];
    const float* W_e   = (const float*)d_in[2];
    const float* Wih_f = (const float*)d_in[3];
    const float* Whh_f = (const float*)d_in[4];
    const float* bih_f = (const float*)d_in[5];
    const float* bhh_f = (const float*)d_in[6];
    const float* Wih_b = (const float*)d_in[7];
    const float* Whh_b = (const float*)d_in[8];
    const float* bih_b = (const float*)d_in[9];
    const float* bhh_b = (const float*)d_in[10];
    const float* Wih   = (const float*)d_in[11];
    const float* Whh   = (const float*)d_in[12];
    const float* bih   = (const float*)d_in[13];
    const float* bhh   = (const float*)d_in[14];
    const int*   walks = (const int*)d_in[15];
    const int*   eids  = (const int*)d_in[16];
    const int*   deg   = (const int*)d_in[17];
    float* out = (float*)d_out;

    dim3 tr_grid(192, 6);
    transpose_all_kernel<<<tr_grid, 256>>>(Whh_f, Whh_b, Whh, Wih);
    wcomb_kernel<<<(GG * EFD + 255) / 256, 256>>>(Wih, W_e);
    bpack_kernel<<<48, 256>>>();

    reset_kernel<<<(NCODE + 255) / 256, 256>>>();
    u2code_kernel<<<(BB + 127) / 128, 128>>>(walks, deg);
    compact_kernel<<<(NCODE + 255) / 256, 256>>>();
    patmap_kernel<<<(BB + 255) / 256, 256>>>();

    // EG via fp16 split mma (the controlled tensor-path experiment)
    eg_mma_kernel<<<NEG / 16, 128>>>(e);
    // HG via proven scalar core
    gemm3_hg_kernel<<<(NN + 15) / 16, 128>>>(h);

    dim3 wgrid(PMAX / 16, 2);
    walk_fused_kernel<<<wgrid, 128>>>(Wih_f, bih_f, bhh_f, Wih_b, bih_b, bhh_b);
    hwalk_pat_kernel<<<(PMAX * OO + 255) / 256, 256>>>();

    dim3 xg_grid(PMAX / 16, LL);
    xge_pat_kernel<<<xg_grid, 128>>>(bih);

    main_fused_kernel<<<BB / 16, 128>>>(eids, walks, deg, bih, bhh, out);
}

// round 17
// speedup vs baseline: 4.2452x; 1.2428x over previous
#include <cuda_runtime.h>
#include <cuda_fp16.h>
#include <math.h>

#define SS   4
#define NN   5000
#define LL   8
#define OO   128
#define EFD  64
#define NEG  80000
#define DIN_ 385
#define BB   20000
#define GG   384

#define NCODE 40320
#define PMAX  4224

typedef unsigned long long u64;

// ---------------- device scratch (static; no allocs allowed) ----------------
__device__ __align__(16) float g_Wt4_f[32 * GG * 4];
__device__ __align__(16) float g_Wt4_b[32 * GG * 4];
__device__ __align__(16) float g_Wt4_m[32 * GG * 4];
__device__ __align__(16) float g_WA4[32 * GG * 4];
__device__ __align__(16) float g_WB4[32 * GG * 4];
__device__ __align__(16) float g_WC4[32 * GG * 4];
__device__ __align__(16) float g_Wcomb[GG * EFD];
__device__ __align__(16) unsigned g_BpkHi[48 * 4 * 32 * 2];   // EG B frags (K=64)
__device__ __align__(16) unsigned g_BpkLo[48 * 4 * 32 * 2];
__device__ __align__(16) unsigned g_BpkMHi[48 * 8 * 32 * 2];  // main Whh frags (K=128)
__device__ __align__(16) unsigned g_BpkMLo[48 * 8 * 32 * 2];
__device__ __align__(16) float g_wD[GG];
__device__ __align__(16) float g_EG[(size_t)NEG * GG];
__device__ __align__(16) float g_HG[(size_t)NN * GG];
__device__ __align__(16) float g_ypf[(size_t)LL * PMAX * OO];
__device__ __align__(16) float g_ypb[(size_t)LL * PMAX * OO];
__device__ __align__(16) float g_XGp[(size_t)LL * PMAX * GG];
__device__ __align__(16) float g_hwp[(size_t)PMAX * OO];
__device__ int g_code[BB];
__device__ int g_pat[BB];
__device__ int g_present[NCODE];
__device__ int g_code2slot[NCODE];
__device__ int g_slot2code[PMAX];
__device__ int g_patcount;
__device__ int g_degmax;

__device__ __constant__ int FACTD[8] = {1, 1, 2, 6, 24, 120, 720, 5040};

// ---------------- fast activations ----------------
__device__ __forceinline__ float sigf(float x) {
    float t;
    asm("ex2.approx.f32 %0, %1;" : "=f"(t) : "f"(x * -1.442695040888963f));
    float r;
    asm("rcp.approx.f32 %0, %1;" : "=f"(r) : "f"(1.0f + t));
    return r;
}
__device__ __forceinline__ float tanhf_fast(float x) {
    return fmaf(2.0f, sigf(2.0f * x), -1.0f);
}

// ---------------- packed f32x2 helpers (scalar core) ----------
__device__ __forceinline__ void ffma2(u64& d, u64 a, u64 b) {
    asm("fma.rn.f32x2 %0, %1, %2, %0;" : "+l"(d) : "l"(a), "l"(b));
}
__device__ __forceinline__ u64 dup2(float w) {
    u64 r; asm("mov.b64 %0, {%1, %1};" : "=l"(r) : "f"(w)); return r;
}
__device__ __forceinline__ u64 pack2u(unsigned x, unsigned y) {
    u64 r; asm("mov.b64 %0, {%1, %2};" : "=l"(r) : "r"(x), "r"(y)); return r;
}
__device__ __forceinline__ float2 unpack2(u64 v) {
    float2 r; asm("mov.b64 {%0, %1}, %2;" : "=f"(r.x), "=f"(r.y) : "l"(v)); return r;
}

#define ROWP 20

template <int KD4>
__device__ __forceinline__ void gemm2_tile16(
    const float* __restrict__ shT, const float* __restrict__ Wt4, int j,
    u64 (&aR)[8], u64 (&aZ)[8], u64 (&aN)[8])
{
#pragma unroll 2
    for (int k4 = 0; k4 < KD4; ++k4) {
        const float4 wa = *reinterpret_cast<const float4*>(Wt4 + ((size_t)k4 * GG + j) * 4);
        const float4 wb = *reinterpret_cast<const float4*>(Wt4 + ((size_t)k4 * GG + 128 + j) * 4);
        const float4 wc = *reinterpret_cast<const float4*>(Wt4 + ((size_t)k4 * GG + 256 + j) * 4);
        const float wfa[4] = {wa.x, wa.y, wa.z, wa.w};
        const float wfb[4] = {wb.x, wb.y, wb.z, wb.w};
        const float wfc[4] = {wc.x, wc.y, wc.z, wc.w};
#pragma unroll
        for (int kk = 0; kk < 4; ++kk) {
            const u64 dra = dup2(wfa[kk]);
            const u64 drb = dup2(wfb[kk]);
            const u64 drc = dup2(wfc[kk]);
            const uint4* ab = reinterpret_cast<const uint4*>(shT + (size_t)(k4 * 4 + kk) * ROWP);
#pragma unroll
            for (int q = 0; q < 4; ++q) {
                const uint4 v = ab[q];
                const u64 a0 = pack2u(v.x, v.y);
                const u64 a1 = pack2u(v.z, v.w);
                ffma2(aR[2 * q],     a0, dra);
                ffma2(aR[2 * q + 1], a1, dra);
                ffma2(aZ[2 * q],     a0, drb);
                ffma2(aZ[2 * q + 1], a1, drb);
                ffma2(aN[2 * q],     a0, drc);
                ffma2(aN[2 * q + 1], a1, drc);
            }
        }
    }
}

// ---------------- prep kernels ----------------
__global__ void transpose_all_kernel(
    const float* __restrict__ Whh_f, const float* __restrict__ Whh_b,
    const float* __restrict__ Whh,   const float* __restrict__ Wih)
{
    int idx = blockIdx.x * 256 + threadIdx.x;
    if (idx >= GG * 128) return;
    int which = blockIdx.y;
    int g = idx >> 7;
    int k = idx & 127;
    const float* W;
    int ldw, koff;
    float* dst;
    switch (which) {
        case 0: W = Whh_f; ldw = 128; koff = 0;   dst = g_Wt4_f; break;
        case 1: W = Whh_b; ldw = 128; koff = 0;   dst = g_Wt4_b; break;
        case 2: W = Whh;   ldw = 128; koff = 0;   dst = g_Wt4_m; break;
        case 3: W = Wih;   ldw = 385; koff = 0;   dst = g_WA4;  break;
        case 4: W = Wih;   ldw = 385; koff = 128; dst = g_WB4;  break;
        default: W = Wih;  ldw = 385; koff = 256; dst = g_WC4;  break;
    }
    float v = W[(size_t)g * ldw + koff + k];
    dst[(((size_t)(k >> 2)) * GG + g) * 4 + (k & 3)] = v;
}

__global__ void wcomb_kernel(const float* __restrict__ Wih, const float* __restrict__ We)
{
    int idx = blockIdx.x * 256 + threadIdx.x;
    if (idx >= GG * EFD) return;
    int g = idx / EFD, c = idx % EFD;
    float s = 0.f;
    for (int d = 0; d < DIN_; ++d)
        s = fmaf(Wih[(size_t)g * DIN_ + d], We[(size_t)d * EFD + c], s);
    g_Wcomb[(size_t)g * EFD + c] = s;
    if (c == 0) g_wD[g] = Wih[(size_t)g * DIN_ + (DIN_ - 1)];
}

#define H2PK(h0v, h1v) ((unsigned)__half_as_ushort(h0v) | ((unsigned)__half_as_ushort(h1v) << 16))

// pack Wcomb into fp16 hi/lo B-frags (EG, K=64): [48][4][32][2]
__global__ void bpack_kernel()
{
    int idx = blockIdx.x * 256 + threadIdx.x;
    if (idx >= 48 * 4 * 32 * 2) return;
    int rp    = idx & 1;
    int lane  = (idx >> 1) & 31;
    int ks    = (idx >> 6) & 3;
    int ntile = idx >> 8;
    int n = ntile * 8 + (lane >> 2);
    int k = ks * 16 + (lane & 3) * 2 + rp * 8;
    float x0 = g_Wcomb[(size_t)n * EFD + k];
    float x1 = g_Wcomb[(size_t)n * EFD + k + 1];
    __half h0 = __float2half_rn(x0), h1 = __float2half_rn(x1);
    g_BpkHi[idx] = H2PK(h0, h1);
    __half l0 = __float2half_rn(x0 - __half2float(h0));
    __half l1 = __float2half_rn(x1 - __half2float(h1));
    g_BpkLo[idx] = H2PK(l0, l1);
}

// pack Whh into fp16 hi/lo B-frags (main, K=128): [48][8][32][2]
__global__ void bpack_main_kernel(const float* __restrict__ Whh)
{
    int idx = blockIdx.x * 256 + threadIdx.x;
    if (idx >= 48 * 8 * 32 * 2) return;
    int rp    = idx & 1;
    int lane  = (idx >> 1) & 31;
    int ks    = (idx >> 6) & 7;
    int ntile = idx >> 9;
    int n = ntile * 8 + (lane >> 2);
    int k = ks * 16 + (lane & 3) * 2 + rp * 8;
    float x0 = Whh[(size_t)n * 128 + k];
    float x1 = Whh[(size_t)n * 128 + k + 1];
    __half h0 = __float2half_rn(x0), h1 = __float2half_rn(x1);
    g_BpkMHi[idx] = H2PK(h0, h1);
    __half l0 = __float2half_rn(x0 - __half2float(h0));
    __half l1 = __float2half_rn(x1 - __half2float(h1));
    g_BpkMLo[idx] = H2PK(l0, l1);
}

__global__ void reset_kernel()
{
    int i = blockIdx.x * 256 + threadIdx.x;
    if (i < NCODE) g_present[i] = 0;
    if (i == 0) { g_patcount = 0; g_degmax = 0; }
}

__global__ void u2code_kernel(const int* __restrict__ walks, const int* __restrict__ deg)
{
    int b = blockIdx.x * 128 + threadIdx.x;
    if (b >= BB) return;
    int w[LL];
    int dmax = 0;
#pragma unroll
    for (int t = 0; t < LL; ++t) {
        w[t] = walks[(size_t)b * LL + t];
        dmax = max(dmax, deg[w[t]]);
    }
    int code = 0;
#pragma unroll
    for (int t = 1; t < LL; ++t) {
        int f = t;
#pragma unroll
        for (int jj = LL - 1; jj >= 0; --jj)
            if (jj <= t && w[jj] == w[t]) f = jj;
        code += f * FACTD[t];
    }
    g_code[b] = code;
    g_present[code] = 1;
    for (int off = 16; off; off >>= 1) dmax = max(dmax, __shfl_xor_sync(0xffffffffu, dmax, off));
    if ((threadIdx.x & 31) == 0) atomicMax(&g_degmax, dmax);
}

__global__ void compact_kernel()
{
    int c = blockIdx.x * 256 + threadIdx.x;
    if (c >= NCODE) return;
    if (g_present[c]) {
        int slot = atomicAdd(&g_patcount, 1);
        g_slot2code[slot] = c;
        g_code2slot[c] = slot;
    }
}

__global__ void patmap_kernel()
{
    int b = blockIdx.x * 256 + threadIdx.x;
    if (b < BB) g_pat[b] = g_code2slot[g_code[b]];
}

// ---------------- mma macro (shared) ----------------------------------------
#define MMA16816(Cv, A0, A1, A2, A3, B0, B1)                                \
    asm volatile(                                                           \
        "mma.sync.aligned.m16n8k16.row.col.f32.f16.f16.f32 "                \
        "{%0,%1,%2,%3},{%4,%5,%6,%7},{%8,%9},{%0,%1,%2,%3};"                \
        : "+f"(Cv[0]), "+f"(Cv[1]), "+f"(Cv[2]), "+f"(Cv[3])                \
        : "r"(A0), "r"(A1), "r"(A2), "r"(A3), "r"(B0), "r"(B1))

// ---------------- EG via fp16 split mma (R16-proven) ------------------------
__global__ void __launch_bounds__(128) eg_mma_kernel(const float* __restrict__ e)
{
    __shared__ __align__(16) float sE[16 * 68];
    const int tid = threadIdx.x;
    const int b0 = blockIdx.x * 16;
    for (int i = tid; i < 16 * 16; i += 128) {
        int r = i >> 4, c4 = i & 15;
        float4 v = *reinterpret_cast<const float4*>(e + (size_t)(b0 + r) * EFD + c4 * 4);
        *reinterpret_cast<float4*>(sE + r * 68 + c4 * 4) = v;
    }
    __syncthreads();

    const int w = tid >> 5, lane = tid & 31;
    const int g = lane >> 2, tg = lane & 3;

    float C[12][4];
#pragma unroll
    for (int nt = 0; nt < 12; ++nt)
#pragma unroll
        for (int q = 0; q < 4; ++q) C[nt][q] = 0.f;

#pragma unroll
    for (int ks = 0; ks < 4; ++ks) {
        const int c0 = ks * 16 + tg * 2;
        float x00 = sE[g * 68 + c0],     x01 = sE[g * 68 + c0 + 1];
        float x08 = sE[g * 68 + c0 + 8], x09 = sE[g * 68 + c0 + 9];
        float x10 = sE[(g + 8) * 68 + c0],     x11 = sE[(g + 8) * 68 + c0 + 1];
        float x18 = sE[(g + 8) * 68 + c0 + 8], x19 = sE[(g + 8) * 68 + c0 + 9];
        __half h00 = __float2half_rn(x00), h01 = __float2half_rn(x01);
        __half h08 = __float2half_rn(x08), h09 = __float2half_rn(x09);
        __half h10 = __float2half_rn(x10), h11 = __float2half_rn(x11);
        __half h18 = __float2half_rn(x18), h19 = __float2half_rn(x19);
        unsigned ah0 = H2PK(h00, h01), ah1 = H2PK(h10, h11);
        unsigned ah2 = H2PK(h08, h09), ah3 = H2PK(h18, h19);
        __half l00 = __float2half_rn(x00 - __half2float(h00));
        __half l01 = __float2half_rn(x01 - __half2float(h01));
        __half l08 = __float2half_rn(x08 - __half2float(h08));
        __half l09 = __float2half_rn(x09 - __half2float(h09));
        __half l10 = __float2half_rn(x10 - __half2float(h10));
        __half l11 = __float2half_rn(x11 - __half2float(h11));
        __half l18 = __float2half_rn(x18 - __half2float(h18));
        __half l19 = __float2half_rn(x19 - __half2float(h19));
        unsigned al0 = H2PK(l00, l01), al1 = H2PK(l10, l11);
        unsigned al2 = H2PK(l08, l09), al3 = H2PK(l18, l19);
#pragma unroll
        for (int nt = 0; nt < 12; ++nt) {
            const int ntile = w * 12 + nt;
            const uint2 bh = *reinterpret_cast<const uint2*>(
                g_BpkHi + ((size_t)(ntile * 4 + ks) * 32 + lane) * 2);
            const uint2 bl = *reinterpret_cast<const uint2*>(
                g_BpkLo + ((size_t)(ntile * 4 + ks) * 32 + lane) * 2);
            MMA16816(C[nt], ah0, ah1, ah2, ah3, bh.x, bh.y);
            MMA16816(C[nt], ah0, ah1, ah2, ah3, bl.x, bl.y);
            MMA16816(C[nt], al0, al1, al2, al3, bh.x, bh.y);
        }
    }

#pragma unroll
    for (int nt = 0; nt < 12; ++nt) {
        const int col = (w * 12 + nt) * 8 + tg * 2;
        *reinterpret_cast<float2*>(g_EG + (size_t)(b0 + g) * GG + col) =
            make_float2(C[nt][0], C[nt][1]);
        *reinterpret_cast<float2*>(g_EG + (size_t)(b0 + g + 8) * GG + col) =
            make_float2(C[nt][2], C[nt][3]);
    }
}

// ---------------- HG GEMM (K=128, scalar core) ------------------------------
__global__ void __launch_bounds__(128) gemm3_hg_kernel(const float* __restrict__ A)
{
    constexpr int K = 128;
    const int M = NN;
    __shared__ __align__(16) float shT[K * ROWP];
    const int j  = threadIdx.x;
    const int b0 = blockIdx.x * 16;
    for (int idx = j; idx < 16 * K; idx += 128) {
        int row = idx / K;
        int k   = idx - row * K;
        float v = (b0 + row < M) ? A[(size_t)(b0 + row) * K + k] : 0.f;
        shT[(size_t)k * ROWP + row] = v;
    }
    __syncthreads();

    u64 aR[8], aZ[8], aN[8];
#pragma unroll
    for (int p = 0; p < 8; ++p) { aR[p] = 0ull; aZ[p] = 0ull; aN[p] = 0ull; }
    gemm2_tile16<32>(shT, g_WA4, j, aR, aZ, aN);

#pragma unroll
    for (int p = 0; p < 8; ++p) {
        float2 r = unpack2(aR[p]);
        float2 z = unpack2(aZ[p]);
        float2 n = unpack2(aN[p]);
        if (b0 + 2 * p < M) {
            float* o = g_HG + (size_t)(b0 + 2 * p) * GG;
            o[j] = r.x; o[128 + j] = z.x; o[256 + j] = n.x;
        }
        if (b0 + 2 * p + 1 < M) {
            float* o = g_HG + (size_t)(b0 + 2 * p + 1) * GG;
            o[j] = r.y; o[128 + j] = z.y; o[256 + j] = n.y;
        }
    }
}

// ---------------- pattern walk GRU (scalar, unchanged) ----------------------
__global__ void __launch_bounds__(128) walk_fused_kernel(
    const float* __restrict__ Wih2_f, const float* __restrict__ bih_f,
    const float* __restrict__ bhh_f,
    const float* __restrict__ Wih2_b, const float* __restrict__ bih_b,
    const float* __restrict__ bhh_b)
{
    const int P = g_patcount;
    const int b0 = blockIdx.x * 16;
    if (b0 >= P) return;
    __shared__ __align__(16) float shT[128 * ROWP];
    __shared__ __align__(16) float shu[32];
    const int j = threadIdx.x;
    const int bwd = blockIdx.y;
    float*       ybuf = bwd ? g_ypb : g_ypf;
    const float* Wt4  = bwd ? g_Wt4_b : g_Wt4_f;
    const float* Wih2 = bwd ? Wih2_b : Wih2_f;
    const float* bih  = bwd ? bih_b : bih_f;
    const float* bhh  = bwd ? bhh_b : bhh_f;

    const float wr0 = Wih2[2 * j],         wr1 = Wih2[2 * j + 1];
    const float wz0 = Wih2[2 * (128 + j)], wz1 = Wih2[2 * (128 + j) + 1];
    const float wn0 = Wih2[2 * (256 + j)], wn1 = Wih2[2 * (256 + j) + 1];
    const float br = bih[j], bz = bih[128 + j], bn = bih[256 + j];
    const float cr = bhh[j], cz = bhh[128 + j], cn = bhh[256 + j];

    int mycode = 0;
    if (j < 16 && b0 + j < P) mycode = g_slot2code[b0 + j];

    float hv[16];
#pragma unroll
    for (int i = 0; i < 16; ++i) hv[i] = 0.f;

    for (int t = 0; t < LL; ++t) {
        const int jj = bwd ? t : (LL - 1 - t);
        if (t > 0) {
#pragma unroll
            for (int i = 0; i < 16; ++i) shT[(size_t)j * ROWP + i] = hv[i];
        }
        if (j < 16) {
            int f = (mycode / FACTD[jj]) % (jj + 1);
            float a = (float)f * (6.283185307179586f / (float)LL);
            shu[2 * j]     = sinf(a);
            shu[2 * j + 1] = cosf(a);
        }
        __syncthreads();

        u64 aR[8], aZ[8], aN[8];
#pragma unroll
        for (int p = 0; p < 8; ++p) { aR[p] = 0ull; aZ[p] = 0ull; aN[p] = 0ull; }
        if (t > 0) gemm2_tile16<32>(shT, Wt4, j, aR, aZ, aN);

        float* yo = ybuf + (size_t)t * PMAX * OO + (size_t)b0 * OO + j;
#pragma unroll
        for (int p = 0; p < 8; ++p) {
            const float4 uv = *reinterpret_cast<const float4*>(shu + 4 * p);
            float2 fR = unpack2(aR[p]);
            float2 fZ = unpack2(aZ[p]);
            float2 fN = unpack2(aN[p]);
            {
                float rg = sigf(fmaf(wr0, uv.x, fmaf(wr1, uv.y, br)) + fR.x + cr);
                float zg = sigf(fmaf(wz0, uv.x, fmaf(wz1, uv.y, bz)) + fZ.x + cz);
                float ng = tanhf_fast(fmaf(wn0, uv.x, fmaf(wn1, uv.y, bn)) + rg * (fN.x + cn));
                hv[2 * p] = (1.f - zg) * ng + zg * hv[2 * p];
                if (b0 + 2 * p < P) yo[(size_t)(2 * p) * 128] = hv[2 * p];
            }
            {
                float rg = sigf(fmaf(wr0, uv.z, fmaf(wr1, uv.w, br)) + fR.y + cr);
                float zg = sigf(fmaf(wz0, uv.z, fmaf(wz1, uv.w, bz)) + fZ.y + cz);
                float ng = tanhf_fast(fmaf(wn0, uv.z, fmaf(wn1, uv.w, bn)) + rg * (fN.y + cn));
                hv[2 * p + 1] = (1.f - zg) * ng + zg * hv[2 * p + 1];
                if (b0 + 2 * p + 1 < P) yo[(size_t)(2 * p + 1) * 128] = hv[2 * p + 1];
            }
        }
        __syncthreads();
    }
}

__global__ void hwalk_pat_kernel()
{
    int i = blockIdx.x * 256 + threadIdx.x;
    if (i >= PMAX * OO) return;
    if (i < g_patcount * OO)
        g_hwp[i] = 0.5f * (g_ypf[(size_t)(LL - 1) * PMAX * OO + i] +
                           g_ypb[(size_t)(LL - 1) * PMAX * OO + i]);
}

__global__ void __launch_bounds__(128) xge_pat_kernel(const float* __restrict__ bih)
{
    const int P = g_patcount;
    const int b0 = blockIdx.x * 16;
    if (b0 >= P) return;
    __shared__ __align__(16) float shf[128 * ROWP];
    __shared__ __align__(16) float shb[128 * ROWP];
    const int j  = threadIdx.x;
    const int p_ = blockIdx.y;

    {
        const float* f    = g_ypf + ((size_t)p_ * PMAX + b0) * OO;
        const float* bsrc = g_ypb + ((size_t)(LL - 1 - p_) * PMAX + b0) * OO;
#pragma unroll
        for (int i = 0; i < 16; ++i) {
            shf[(size_t)j * ROWP + i] = f[(size_t)i * 128 + j];
            shb[(size_t)j * ROWP + i] = bsrc[(size_t)i * 128 + j];
        }
    }
    __syncthreads();

    u64 aR[8], aZ[8], aN[8];
#pragma unroll
    for (int p = 0; p < 8; ++p) { aR[p] = 0ull; aZ[p] = 0ull; aN[p] = 0ull; }
    gemm2_tile16<32>(shf, g_WB4, j, aR, aZ, aN);
    gemm2_tile16<32>(shb, g_WC4, j, aR, aZ, aN);

    const float br = bih[j], bz = bih[128 + j], bn = bih[256 + j];
    float* out = g_XGp + ((size_t)p_ * PMAX + b0) * GG;
#pragma unroll
    for (int p = 0; p < 8; ++p) {
        float2 r = unpack2(aR[p]);
        float2 z = unpack2(aZ[p]);
        float2 n = unpack2(aN[p]);
        if (b0 + 2 * p < P) {
            float* o = out + (size_t)(2 * p) * GG;
            o[j] = r.x + br; o[128 + j] = z.x + bz; o[256 + j] = n.x + bn;
        }
        if (b0 + 2 * p + 1 < P) {
            float* o = out + (size_t)(2 * p + 1) * GG;
            o[j] = r.y + br; o[128 + j] = z.y + bz; o[256 + j] = n.y + bn;
        }
    }
}

// ---------------- main GRU: 15 steps fused, fp16 split mma ------------------
// block = 32 rows, 256 thr / 8 warps. warp wg owns cols gate*128+wg*16+jt*8,
// jt in {0,1}, over both 16-row mtiles. C[2][3][2][4] = 48 floats (proven).
// h published per step as pre-split hi/lo half2 pairs in smem [32][68].
__global__ void __launch_bounds__(256) main_mma_fused_kernel(
    const int* __restrict__ eids, const int* __restrict__ walks,
    const int* __restrict__ deg,
    const float* __restrict__ bih, const float* __restrict__ bhh,
    float* __restrict__ dout)
{
    __shared__ __align__(16) unsigned sHi[32 * 68];
    __shared__ __align__(16) unsigned sLo[32 * 68];
    __shared__ int   sx[32];
    __shared__ int   snode[32];
    __shared__ float sdv[32];
    const int tid = threadIdx.x;
    const int wg = tid >> 5, lane = tid & 31;
    const int g = lane >> 2, tg = lane & 3;
    const int b0 = blockIdx.x * 32;

    // thread-owned h: rows i*8+g (i=0..3), col pairs wg*16+jt*8+2tg (jt=0,1)
    float hv[4][2][2];
#pragma unroll
    for (int i = 0; i < 4; ++i) {
        const int row = b0 + i * 8 + g;
        const float* hp = g_hwp + (size_t)g_pat[row] * OO;
#pragma unroll
        for (int jt = 0; jt < 2; ++jt) {
            float2 v = *reinterpret_cast<const float2*>(hp + wg * 16 + jt * 8 + 2 * tg);
            hv[i][jt][0] = v.x; hv[i][jt][1] = v.y;
        }
    }

    const int dm = g_degmax;
    const float inv_dm = (dm > 0) ? (1.f / (float)dm) : 0.f;

    for (int t = 0; t < 2 * LL - 1; ++t) {
        const int even = ((t & 1) == 0);
        const int p = even ? (t >> 1) : ((t - 1) >> 1);

        // publish h as split hi/lo half2 pairs
#pragma unroll
        for (int i = 0; i < 4; ++i) {
            const int r = i * 8 + g;
#pragma unroll
            for (int jt = 0; jt < 2; ++jt) {
                float x0 = hv[i][jt][0], x1 = hv[i][jt][1];
                __half h0 = __float2half_rn(x0), h1 = __float2half_rn(x1);
                __half l0 = __float2half_rn(x0 - __half2float(h0));
                __half l1 = __float2half_rn(x1 - __half2float(h1));
                const int pc = r * 68 + wg * 8 + jt * 4 + tg;
                sHi[pc] = H2PK(h0, h1);
                sLo[pc] = H2PK(l0, l1);
            }
        }
        if (tid < 32) {
            int b = b0 + tid;
            if (even) {
                sx[tid] = g_pat[b];
                int node = walks[(size_t)b * LL + (LL - 1 - p)];
                snode[tid] = node;
                sdv[tid] = (float)deg[node] * inv_dm;
            } else {
                sx[tid] = eids[(size_t)b * (LL - 1) + p];
            }
        }
        __syncthreads();

        float C[2][3][2][4];
#pragma unroll
        for (int mt = 0; mt < 2; ++mt)
#pragma unroll
            for (int ga = 0; ga < 3; ++ga)
#pragma unroll
                for (int jt = 0; jt < 2; ++jt)
#pragma unroll
                    for (int q = 0; q < 4; ++q) C[mt][ga][jt][q] = 0.f;

#pragma unroll
        for (int ks = 0; ks < 8; ++ks) {
            unsigned ah[2][4], al[2][4];
#pragma unroll
            for (int mt = 0; mt < 2; ++mt) {
                const int r0 = (mt * 16 + g) * 68 + ks * 8 + tg;
                const int r1 = (mt * 16 + g + 8) * 68 + ks * 8 + tg;
                ah[mt][0] = sHi[r0];     ah[mt][1] = sHi[r1];
                ah[mt][2] = sHi[r0 + 4]; ah[mt][3] = sHi[r1 + 4];
                al[mt][0] = sLo[r0];     al[mt][1] = sLo[r1];
                al[mt][2] = sLo[r0 + 4]; al[mt][3] = sLo[r1 + 4];
            }
#pragma unroll
            for (int ga = 0; ga < 3; ++ga)
#pragma unroll
                for (int jt = 0; jt < 2; ++jt) {
                    const int ntile = ga * 16 + wg * 2 + jt;
                    const uint2 bh = *reinterpret_cast<const uint2*>(
                        g_BpkMHi + ((size_t)(ntile * 8 + ks) * 32 + lane) * 2);
                    const uint2 bl = *reinterpret_cast<const uint2*>(
                        g_BpkMLo + ((size_t)(ntile * 8 + ks) * 32 + lane) * 2);
                    MMA16816(C[0][ga][jt], ah[0][0], ah[0][1], ah[0][2], ah[0][3], bh.x, bh.y);
                    MMA16816(C[1][ga][jt], ah[1][0], ah[1][1], ah[1][2], ah[1][3], bh.x, bh.y);
                    MMA16816(C[0][ga][jt], ah[0][0], ah[0][1], ah[0][2], ah[0][3], bl.x, bl.y);
                    MMA16816(C[1][ga][jt], ah[1][0], ah[1][1], ah[1][2], ah[1][3], bl.x, bl.y);
                    MMA16816(C[0][ga][jt], al[0][0], al[0][1], al[0][2], al[0][3], bh.x, bh.y);
                    MMA16816(C[1][ga][jt], al[1][0], al[1][1], al[1][2], al[1][3], bh.x, bh.y);
                }
        }

        // epilogue: GRU update for thread-owned (row, colpair) positions
#pragma unroll
        for (int mt = 0; mt < 2; ++mt)
#pragma unroll
            for (int q2 = 0; q2 < 2; ++q2) {
                const int i = mt * 2 + q2;
                const int rloc = i * 8 + g;
                const float* xb;
                const float* hg = 0;
                float d = 0.f;
                if (even) {
                    xb = g_XGp + ((size_t)p * PMAX + sx[rloc]) * GG;
                    hg = g_HG + (size_t)snode[rloc] * GG;
                    d  = sdv[rloc];
                } else {
                    xb = g_EG + (size_t)sx[rloc] * GG;
                }
#pragma unroll
                for (int jt = 0; jt < 2; ++jt) {
                    const int c = wg * 16 + jt * 8 + 2 * tg;
                    float2 xr = *reinterpret_cast<const float2*>(xb + c);
                    float2 xz = *reinterpret_cast<const float2*>(xb + 128 + c);
                    float2 xn = *reinterpret_cast<const float2*>(xb + 256 + c);
                    float2 crv = *reinterpret_cast<const float2*>(bhh + c);
                    float2 czv = *reinterpret_cast<const float2*>(bhh + 128 + c);
                    float2 cnv = *reinterpret_cast<const float2*>(bhh + 256 + c);
                    if (even) {
                        float2 hgr = *reinterpret_cast<const float2*>(hg + c);
                        float2 hgz = *reinterpret_cast<const float2*>(hg + 128 + c);
                        float2 hgn = *reinterpret_cast<const float2*>(hg + 256 + c);
                        float2 wdr = *reinterpret_cast<const float2*>(g_wD + c);
                        float2 wdz = *reinterpret_cast<const float2*>(g_wD + 128 + c);
                        float2 wdn = *reinterpret_cast<const float2*>(g_wD + 256 + c);
                        xr.x += hgr.x + d * wdr.x; xr.y += hgr.y + d * wdr.y;
                        xz.x += hgz.x + d * wdz.x; xz.y += hgz.y + d * wdz.y;
                        xn.x += hgn.x + d * wdn.x; xn.y += hgn.y + d * wdn.y;
                    } else {
                        float2 brv = *reinterpret_cast<const float2*>(bih + c);
                        float2 bzv = *reinterpret_cast<const float2*>(bih + 128 + c);
                        float2 bnv = *reinterpret_cast<const float2*>(bih + 256 + c);
                        xr.x += brv.x; xr.y += brv.y;
                        xz.x += bzv.x; xz.y += bzv.y;
                        xn.x += bnv.x; xn.y += bnv.y;
                    }
#pragma unroll
                    for (int dd = 0; dd < 2; ++dd) {
                        const int q = q2 * 2 + dd;
                        float aR = C[mt][0][jt][q];
                        float aZ = C[mt][1][jt][q];
                        float aN = C[mt][2][jt][q];
                        float xrv = dd ? xr.y : xr.x;
                        float xzv = dd ? xz.y : xz.x;
                        float xnv = dd ? xn.y : xn.x;
                        float crs = dd ? crv.y : crv.x;
                        float czs = dd ? czv.y : czv.x;
                        float cns = dd ? cnv.y : cnv.x;
                        float rg = sigf(xrv + aR + crs);
                        float zg = sigf(xzv + aZ + czs);
                        float ng = tanhf_fast(xnv + rg * (aN + cns));
                        hv[i][jt][dd] = (1.f - zg) * ng + zg * hv[i][jt][dd];
                    }
                }
            }
        __syncthreads();   // protect sHi/sLo before next step's overwrite
    }

    // write final h
#pragma unroll
    for (int i = 0; i < 4; ++i) {
        const int row = b0 + i * 8 + g;
#pragma unroll
        for (int jt = 0; jt < 2; ++jt) {
            *reinterpret_cast<float2*>(dout + (size_t)row * OO + wg * 16 + jt * 8 + 2 * tg) =
                make_float2(hv[i][jt][0], hv[i][jt][1]);
        }
    }
}

// ---------------------------------------------------------------------------
extern "C" void kernel_launch(void* const* d_in, const int* in_sizes, int n_in,
                              void* d_out, int out_size)
{
    (void)in_sizes; (void)n_in; (void)out_size;
    const float* h     = (const float*)d_in[0];
    const float* e     = (const float*)d_in[1];
    const float* W_e   = (const float*)d_in[2];
    const float* Wih_f = (const float*)d_in[3];
    const float* Whh_f = (const float*)d_in[4];
    const float* bih_f = (const float*)d_in[5];
    const float* bhh_f = (const float*)d_in[6];
    const float* Wih_b = (const float*)d_in[7];
    const float* Whh_b = (const float*)d_in[8];
    const float* bih_b = (const float*)d_in[9];
    const float* bhh_b = (const float*)d_in[10];
    const float* Wih   = (const float*)d_in[11];
    const float* Whh   = (const float*)d_in[12];
    const float* bih   = (const float*)d_in[13];
    const float* bhh   = (const float*)d_in[14];
    const int*   walks = (const int*)d_in[15];
    const int*   eids  = (const int*)d_in[16];
    const int*   deg   = (const int*)d_in[17];
    float* out = (float*)d_out;

    dim3 tr_grid(192, 6);
    transpose_all_kernel<<<tr_grid, 256>>>(Whh_f, Whh_b, Whh, Wih);
    wcomb_kernel<<<(GG * EFD + 255) / 256, 256>>>(Wih, W_e);
    bpack_kernel<<<48, 256>>>();
    bpack_main_kernel<<<96, 256>>>(Whh);

    reset_kernel<<<(NCODE + 255) / 256, 256>>>();
    u2code_kernel<<<(BB + 127) / 128, 128>>>(walks, deg);
    compact_kernel<<<(NCODE + 255) / 256, 256>>>();
    patmap_kernel<<<(BB + 255) / 256, 256>>>();

    eg_mma_kernel<<<NEG / 16, 128>>>(e);
    gemm3_hg_kernel<<<(NN + 15) / 16, 128>>>(h);

    dim3 wgrid(PMAX / 16, 2);
    walk_fused_kernel<<<wgrid, 128>>>(Wih_f, bih_f, bhh_f, Wih_b, bih_b, bhh_b);
    hwalk_pat_kernel<<<(PMAX * OO + 255) / 256, 256>>>();

    dim3 xg_grid(PMAX / 16, LL);
    xge_pat_kernel<<<xg_grid, 128>>>(bih);

    // main GRU: 15 steps fused, fp16 split mma
    main_mma_fused_kernel<<<BB / 32, 256>>>(eids, walks, deg, bih, bhh, out);
}